// round 7
// baseline (speedup 1.0000x reference)
#include <cuda_runtime.h>
#include <cuda_bf16.h>
#include <math.h>
#include <stdint.h>

#define BSZ   16384
#define LSP   32
#define C1    128
#define C2    64
#define CH2   16

// ---- persistent device scratch ----
__device__ float  g_images[BSZ * LSP];
__device__ float  g_h2[BSZ * C2 * LSP];
__device__ double g_stats1[2 * C1];
__device__ double g_stats2[2 * C2];
__device__ float  g_a1[C1], g_c1[C1];
__device__ float  g_a2[C2], g_c2[C2];

// ================================================================
__global__ void k_zero_stats() {
    int t = threadIdx.x;
    if (t < 2 * C1) g_stats1[t] = 0.0;
    if (t < 2 * C2) g_stats2[t] = 0.0;
}

// ------------------------------------------------------------------
// given = probs[:8]/max(probs[:8]) (sum-normalization cancels).
__global__ void k_images(const float* __restrict__ x, const float* __restrict__ qp) {
    int t = blockIdx.x * blockDim.x + threadIdx.x;
    if (t >= BSZ * 4) return;
    int b = t >> 2, g = t & 3;
    float c[4], s[4];
#pragma unroll
    for (int q = 0; q < 4; q++) {
        float th = 0.5f * (x[b * 4 + q] + qp[g * 4 + q]);
        c[q] = cosf(th);
        s[q] = sinf(th);
    }
    float p[8];
    float mx = 0.f;
#pragma unroll
    for (int i = 0; i < 8; i++) {
        float a = c[0];
        a *= ((i >> 2) & 1) ? s[1] : c[1];
        a *= ((i >> 1) & 1) ? s[2] : c[2];
        a *= (i & 1)        ? s[3] : c[3];
        float pp = a * a;
        p[i] = pp;
        mx = fmaxf(mx, pp);
    }
    float inv = 1.0f / mx;
#pragma unroll
    for (int i = 0; i < 8; i++) g_images[b * 32 + g * 8 + i] = p[i] * inv;
}

// ------------------------------------------------------------------
__global__ void k_conv1_stats(const float* __restrict__ w1, const float* __restrict__ b1) {
    __shared__ float sh[CH2][34];
    int tid = threadIdx.x;
    int b0 = blockIdx.x * CH2;
    for (int i = tid; i < CH2 * 32; i += 128)
        sh[i >> 5][(i & 31) + 1] = g_images[(b0 + (i >> 5)) * 32 + (i & 31)];
    if (tid < CH2) { sh[tid][0] = 0.f; sh[tid][33] = 0.f; }
    __syncthreads();

    int oc = tid;
    float wA = w1[oc * 3 + 2], wB = w1[oc * 3 + 1], wC = w1[oc * 3 + 0], bb = b1[oc];
    float sum = 0.f, sq = 0.f;
    for (int r = 0; r < CH2; r++) {
#pragma unroll
        for (int p = 0; p < 32; p++) {
            float y = bb + sh[r][p] * wA + sh[r][p + 1] * wB + sh[r][p + 2] * wC;
            y = fmaxf(y, 0.f);
            sum += y;
            sq += y * y;
        }
    }
    atomicAdd(&g_stats1[oc], (double)sum);
    atomicAdd(&g_stats1[C1 + oc], (double)sq);
}

// ------------------------------------------------------------------
__global__ void k_fin1(const float* __restrict__ gamma, const float* __restrict__ beta) {
    int c = threadIdx.x;
    if (c >= C1) return;
    double N = (double)BSZ * LSP;
    double mean = g_stats1[c] / N;
    double var = g_stats1[C1 + c] / N - mean * mean;
    float a = gamma[c] * (float)(1.0 / sqrt(var + 1e-5));
    g_a1[c] = a;
    g_c1[c] = beta[c] - (float)mean * a;
}

__global__ void k_fin2(const float* __restrict__ gamma, const float* __restrict__ beta) {
    int c = threadIdx.x;
    if (c >= C2) return;
    double N = (double)BSZ * LSP;
    double mean = g_stats2[c] / N;
    double var = g_stats2[C2 + c] / N - mean * mean;
    float a = gamma[c] * (float)(1.0 / sqrt(var + 1e-5));
    g_a2[c] = a;
    g_c2[c] = beta[c] - (float)mean * a;
}

// ------------------------------------------------------------------
// conv2 via mma.sync m16n8k32 s8 with 16-bit fixed-point split:
//   A_q = round(A*qa) = 256*AH + AL  (AH,AL signed, AL zero-mean)
//   D = (65536*sum AH*BH + 256*sum(AH*BL + AL*BH)) / (qa*qb)   [AL*BL dropped]
// Per CTA: 4 batch rows, M=128 pos x N=64 oc, K=3 taps x 128 ic.
// A stored once per ic; tap shift lives in the address (halo-padded rows).
// smem word offsets:
#define OFF_AH 0          // [bl4][q0 0..33][icw 0..31 pad->36] = 4896
#define OFF_AL 4896
#define OFF_BB 9792       // 2 bufs x (BH 2304 + BL 2304) = 9216
#define OFF_H1 19008      // fp32 h1n [bl][q0][ic] = 17408
#define OFF_SP 36416      // 128*6
#define OFF_SIMG 37184    // 4*34
#define OFF_RED 37320     // 128
#define OFF_MAX 37448     // [0]=maxA bits, [1..3]=maxB per tap
#define SM_FLOATS 37452   // 149808 bytes

__device__ __forceinline__ void imma16832(int* d, uint32_t a0, uint32_t a1,
                                          uint32_t a2, uint32_t a3,
                                          uint32_t b0, uint32_t b1) {
    asm volatile(
        "mma.sync.aligned.m16n8k32.row.col.s32.s8.s8.s32 "
        "{%0,%1,%2,%3},{%4,%5,%6,%7},{%8,%9},{%0,%1,%2,%3};"
        : "+r"(d[0]), "+r"(d[1]), "+r"(d[2]), "+r"(d[3])
        : "r"(a0), "r"(a1), "r"(a2), "r"(a3), "r"(b0), "r"(b1));
}

__device__ __forceinline__ void quant_pack(const float* src, float q,
                                           uint32_t& whi, uint32_t& wlo) {
    uint32_t hi = 0, lo = 0;
#pragma unroll
    for (int i = 0; i < 4; i++) {
        int v = __float2int_rn(src[i] * q);
        int h = (v + 128) >> 8;
        int l = v - (h << 8);
        hi |= ((uint32_t)h & 0xFFu) << (8 * i);
        lo |= ((uint32_t)l & 0xFFu) << (8 * i);
    }
    whi = hi; wlo = lo;
}

__global__ void __launch_bounds__(512, 1)
k_conv2(const float* __restrict__ w1, const float* __restrict__ b1,
        const float* __restrict__ w2, const float* __restrict__ b2) {
    extern __shared__ float sm[];
    uint32_t* sAH = (uint32_t*)(sm + OFF_AH);
    uint32_t* sAL = (uint32_t*)(sm + OFF_AL);
    uint32_t* sBB = (uint32_t*)(sm + OFF_BB);
    float* sH1  = sm + OFF_H1;
    float* sp   = sm + OFF_SP;
    float* simg = sm + OFF_SIMG;
    float* red  = sm + OFF_RED;
    uint32_t* smax = (uint32_t*)(sm + OFF_MAX);

    int tid = threadIdx.x;
    int wid = tid >> 5, lid = tid & 31;
    int rA = lid >> 2, cA = lid & 3;     // lane row / byte-col
    int g = lid >> 2, q = lid & 3;
    int bbase = blockIdx.x * 4;

    // --- phase 0: params, images, init ---
    if (tid < 128) red[tid] = 0.f;
    if (tid < 4) smax[tid] = 0u;
    for (int i = tid; i < 128; i += 512) {
        sp[i * 6 + 0] = w1[i * 3 + 0];
        sp[i * 6 + 1] = w1[i * 3 + 1];
        sp[i * 6 + 2] = w1[i * 3 + 2];
        sp[i * 6 + 3] = b1[i];
        sp[i * 6 + 4] = g_a1[i];
        sp[i * 6 + 5] = g_c1[i];
    }
    for (int i = tid; i < 4 * 32; i += 512) {
        int bl = i >> 5, p = i & 31;
        simg[bl * 34 + p + 1] = g_images[(bbase + bl) * 32 + p];
    }
    if (tid < 4) { simg[tid * 34] = 0.f; simg[tid * 34 + 33] = 0.f; }
    __syncthreads();

    // --- phase 1: h1n fp32 + maxima ---
    {
        float lmA = 0.f;
        for (int idx = tid; idx < 4 * 34 * 128; idx += 512) {
            int bl = idx / 4352, r = idx - bl * 4352;
            int q0 = r >> 7, ic = r & 127;
            float v = 0.f;
            if (q0 >= 1 && q0 <= 32) {
                int p = q0 - 1;
                const float* pp = &sp[ic * 6];
                float y = pp[3] + simg[bl * 34 + p] * pp[2]
                                + simg[bl * 34 + p + 1] * pp[1]
                                + simg[bl * 34 + p + 2] * pp[0];
                y = fmaxf(y, 0.f);
                v = fmaf(pp[4], y, pp[5]);
            }
            sH1[(bl * 34 + q0) * 128 + ic] = v;
            lmA = fmaxf(lmA, fabsf(v));
        }
        atomicMax(&smax[0], __float_as_uint(lmA));
        float lb0 = 0.f, lb1 = 0.f, lb2 = 0.f;
        for (int i = tid; i < 128 * 64 * 3; i += 512) {
            float v = fabsf(w2[i]);
            int kk = i % 3;                 // tap = 2 - kk
            if (kk == 2) lb0 = fmaxf(lb0, v);
            else if (kk == 1) lb1 = fmaxf(lb1, v);
            else lb2 = fmaxf(lb2, v);
        }
        atomicMax(&smax[1], __float_as_uint(lb0));
        atomicMax(&smax[2], __float_as_uint(lb1));
        atomicMax(&smax[3], __float_as_uint(lb2));
    }
    __syncthreads();

    float maxA = fmaxf(__uint_as_float(smax[0]), 1e-20f);
    float maxB[3];
#pragma unroll
    for (int t = 0; t < 3; t++) maxB[t] = fmaxf(__uint_as_float(smax[1 + t]), 1e-20f);
    float qa = 32512.f / maxA;

    // --- phase 2: quantize A + stage B(tap0) into buf0 ---
    for (int idx = tid; idx < 4 * 34 * 32; idx += 512) {
        int bl = idx / 1088, r = idx - bl * 1088;
        int q0 = r >> 5, icw = r & 31;
        float v4[4];
#pragma unroll
        for (int i = 0; i < 4; i++) v4[i] = sH1[(bl * 34 + q0) * 128 + 4 * icw + i];
        uint32_t whi, wlo;
        quant_pack(v4, qa, whi, wlo);
        int o = (bl * 34 + q0) * 36 + icw;
        sAH[o] = whi; sAL[o] = wlo;
    }
    {
        float qb = 32512.f / maxB[0];
        for (int idx = tid; idx < 64 * 32; idx += 512) {
            int n = idx >> 5, icw = idx & 31;
            float v4[4];
#pragma unroll
            for (int i = 0; i < 4; i++) v4[i] = w2[(4 * icw + i) * 192 + n * 3 + 2];
            uint32_t whi, wlo;
            quant_pack(v4, qb, whi, wlo);
            sBB[n * 36 + icw] = whi;
            sBB[2304 + n * 36 + icw] = wlo;
        }
    }
    __syncthreads();

    // --- main loop: warp tile 32 rows (bl) x 16 oc ---
    int bl = wid >> 2;
    int n0 = (wid & 3) * 16;

    int accHH[2][2][4], accX[2][2][4];
    float master[2][2][4];
#pragma unroll
    for (int mt = 0; mt < 2; mt++)
#pragma unroll
        for (int j = 0; j < 2; j++)
#pragma unroll
            for (int v = 0; v < 4; v++) {
                accHH[mt][j][v] = 0; accX[mt][j][v] = 0; master[mt][j][v] = 0.f;
            }

    for (int tap = 0; tap < 3; tap++) {
        uint32_t* BH = sBB + (tap & 1) * 4608;
        uint32_t* BL = BH + 2304;
#pragma unroll
        for (int s = 0; s < 4; s++) {
            uint32_t aH[2][4], aL[2][4];
#pragma unroll
            for (int mt = 0; mt < 2; mt++) {
                int r0 = (bl * 34 + mt * 16 + rA + tap) * 36 + 8 * s + cA;
                int r1 = r0 + 8 * 36;
                aH[mt][0] = sAH[r0];     aL[mt][0] = sAL[r0];
                aH[mt][1] = sAH[r1];     aL[mt][1] = sAL[r1];
                aH[mt][2] = sAH[r0 + 4]; aL[mt][2] = sAL[r0 + 4];
                aH[mt][3] = sAH[r1 + 4]; aL[mt][3] = sAL[r1 + 4];
            }
            uint32_t bH[2][2], bL[2][2];
#pragma unroll
            for (int j = 0; j < 2; j++) {
                int nb = (n0 + 8 * j + rA) * 36 + 8 * s + cA;
                bH[j][0] = BH[nb];     bH[j][1] = BH[nb + 4];
                bL[j][0] = BL[nb];     bL[j][1] = BL[nb + 4];
            }
#pragma unroll
            for (int mt = 0; mt < 2; mt++)
#pragma unroll
                for (int j = 0; j < 2; j++) {
                    imma16832(accHH[mt][j], aH[mt][0], aH[mt][1], aH[mt][2], aH[mt][3],
                              bH[j][0], bH[j][1]);
                    imma16832(accX[mt][j], aH[mt][0], aH[mt][1], aH[mt][2], aH[mt][3],
                              bL[j][0], bL[j][1]);
                    imma16832(accX[mt][j], aL[mt][0], aL[mt][1], aL[mt][2], aL[mt][3],
                              bH[j][0], bH[j][1]);
                }
        }
        // fold this tap into fp32 master, reset int accs
        float sc = maxA * maxB[tap] * (1.f / (32512.f * 32512.f));
#pragma unroll
        for (int mt = 0; mt < 2; mt++)
#pragma unroll
            for (int j = 0; j < 2; j++)
#pragma unroll
                for (int v = 0; v < 4; v++) {
                    master[mt][j][v] += ((float)accHH[mt][j][v] * 65536.f
                                       + (float)accX[mt][j][v] * 256.f) * sc;
                    accHH[mt][j][v] = 0; accX[mt][j][v] = 0;
                }
        // stage next tap's B into the other buffer
        if (tap < 2) {
            float qb = 32512.f / maxB[tap + 1];
            uint32_t* NBH = sBB + ((tap + 1) & 1) * 4608;
            for (int idx = tid; idx < 64 * 32; idx += 512) {
                int n = idx >> 5, icw = idx & 31;
                float v4[4];
#pragma unroll
                for (int i = 0; i < 4; i++)
                    v4[i] = w2[(4 * icw + i) * 192 + n * 3 + (1 - tap)];
                uint32_t whi, wlo;
                quant_pack(v4, qb, whi, wlo);
                NBH[n * 36 + icw] = whi;
                NBH[2304 + n * 36 + icw] = wlo;
            }
            __syncthreads();
        }
    }

    // --- epilogue: bias + relu, store h2, per-oc stats ---
    int b = bbase + bl;
    float bias[2][2];
#pragma unroll
    for (int j = 0; j < 2; j++) {
        bias[j][0] = __ldg(&b2[n0 + 8 * j + 2 * q]);
        bias[j][1] = __ldg(&b2[n0 + 8 * j + 2 * q + 1]);
    }
    float ssum[2][2], ssq[2][2];
#pragma unroll
    for (int j = 0; j < 2; j++)
        for (int c = 0; c < 2; c++) { ssum[j][c] = 0.f; ssq[j][c] = 0.f; }

#pragma unroll
    for (int mt = 0; mt < 2; mt++)
#pragma unroll
        for (int j = 0; j < 2; j++)
#pragma unroll
            for (int h = 0; h < 2; h++)
#pragma unroll
                for (int c = 0; c < 2; c++) {
                    int oc = n0 + 8 * j + 2 * q + c;
                    int p = mt * 16 + h * 8 + g;
                    float y = fmaxf(master[mt][j][h * 2 + c] + bias[j][c], 0.f);
                    g_h2[(b * 64 + oc) * 32 + p] = y;
                    ssum[j][c] += y;
                    ssq[j][c]  += y * y;
                }
#pragma unroll
    for (int j = 0; j < 2; j++)
#pragma unroll
        for (int c = 0; c < 2; c++) {
#pragma unroll
            for (int mk = 4; mk <= 16; mk <<= 1) {
                ssum[j][c] += __shfl_xor_sync(0xffffffffu, ssum[j][c], mk);
                ssq[j][c]  += __shfl_xor_sync(0xffffffffu, ssq[j][c], mk);
            }
        }
    if (lid < 4) {
#pragma unroll
        for (int j = 0; j < 2; j++)
#pragma unroll
            for (int c = 0; c < 2; c++) {
                int oc = n0 + 8 * j + 2 * lid + c;
                atomicAdd(&red[oc], ssum[j][c]);
                atomicAdd(&red[64 + oc], ssq[j][c]);
            }
    }
    __syncthreads();
    if (tid < 128) atomicAdd(&g_stats2[tid], (double)red[tid]);
}

// ------------------------------------------------------------------
__global__ void k_conv3(const float* __restrict__ w3, const float* __restrict__ b3,
                        float* __restrict__ out) {
    __shared__ float sa[64], sc[64], swv[192], sb3;
    int tid = threadIdx.x;
    if (tid < 64) { sa[tid] = g_a2[tid]; sc[tid] = g_c2[tid]; }
    if (tid < 192) swv[tid] = w3[tid];
    if (tid == 0) sb3 = b3[0];
    __syncthreads();

    int t = blockIdx.x * 256 + tid;
    int b = t >> 5, p = t & 31;
    const float* base = &g_h2[b * 64 * 32];
    float acc = sb3;
#pragma unroll 4
    for (int ic = 0; ic < 64; ic++) {
        const float* row = base + ic * 32;
        float a = sa[ic], cs = sc[ic];
        float x0 = fmaf(a, row[p], cs);
        float xm = (p > 0)  ? fmaf(a, row[p - 1], cs) : 0.f;
        float xp = (p < 31) ? fmaf(a, row[p + 1], cs) : 0.f;
        acc += xm * swv[ic * 3 + 2] + x0 * swv[ic * 3 + 1] + xp * swv[ic * 3 + 0];
    }
    out[t] = tanhf(acc);
}

// ------------------------------------------------------------------
extern "C" void kernel_launch(void* const* d_in, const int* in_sizes, int n_in,
                              void* d_out, int out_size) {
    const float* x   = (const float*)d_in[0];
    const float* qp  = (const float*)d_in[1];
    const float* w1  = (const float*)d_in[2];
    const float* b1  = (const float*)d_in[3];
    const float* g1  = (const float*)d_in[4];
    const float* be1 = (const float*)d_in[5];
    const float* w2  = (const float*)d_in[6];
    const float* b2  = (const float*)d_in[7];
    const float* g2  = (const float*)d_in[8];
    const float* be2 = (const float*)d_in[9];
    const float* w3  = (const float*)d_in[10];
    const float* b3  = (const float*)d_in[11];
    float* out = (float*)d_out;

    const int smem_bytes = SM_FLOATS * (int)sizeof(float);   // 149808 B
    cudaFuncSetAttribute(k_conv2, cudaFuncAttributeMaxDynamicSharedMemorySize, smem_bytes);

    k_zero_stats<<<1, 256>>>();
    k_images<<<(BSZ * 4) / 256, 256>>>(x, qp);
    k_conv1_stats<<<BSZ / CH2, 128>>>(w1, b1);
    k_fin1<<<1, 128>>>(g1, be1);
    k_conv2<<<BSZ / 4, 512, smem_bytes>>>(w1, b1, w2, b2);
    k_fin2<<<1, 64>>>(g2, be2);
    k_conv3<<<(BSZ * 32) / 256, 256>>>(w3, b3, out);
}

// round 8
// speedup vs baseline: 2.3074x; 2.3074x over previous
#include <cuda_runtime.h>
#include <cuda_bf16.h>
#include <math.h>
#include <stdint.h>

#define BSZ   16384
#define LSP   32
#define C1    128
#define C2    64
#define CH2   16

// ---- persistent device scratch ----
__device__ float  g_images[BSZ * LSP];
__device__ float  g_h2[BSZ * C2 * LSP];
__device__ double g_stats1[2 * C1];
__device__ double g_stats2[2 * C2];
__device__ float  g_a1[C1], g_c1[C1];
__device__ float  g_a2[C2], g_c2[C2];

// pack two floats as bf16x2: low 16 bits = `even`, high = `odd`
__device__ __forceinline__ uint32_t packbf(float even, float odd) {
    uint32_t r;
    asm("cvt.rn.bf16x2.f32 %0, %1, %2;" : "=r"(r) : "f"(odd), "f"(even));
    return r;
}
__device__ __forceinline__ float bf16f(float v) {
    return __bfloat162float(__float2bfloat16_rn(v));
}

// ================================================================
__global__ void k_zero_stats() {
    int t = threadIdx.x;
    if (t < 2 * C1) g_stats1[t] = 0.0;
    if (t < 2 * C2) g_stats2[t] = 0.0;
}

// ------------------------------------------------------------------
// given = probs[:8]/max(probs[:8]) (sum-normalization cancels).
__global__ void k_images(const float* __restrict__ x, const float* __restrict__ qp) {
    int t = blockIdx.x * blockDim.x + threadIdx.x;
    if (t >= BSZ * 4) return;
    int b = t >> 2, g = t & 3;
    float c[4], s[4];
#pragma unroll
    for (int q = 0; q < 4; q++) {
        float th = 0.5f * (x[b * 4 + q] + qp[g * 4 + q]);
        c[q] = cosf(th);
        s[q] = sinf(th);
    }
    float p[8];
    float mx = 0.f;
#pragma unroll
    for (int i = 0; i < 8; i++) {
        float a = c[0];
        a *= ((i >> 2) & 1) ? s[1] : c[1];
        a *= ((i >> 1) & 1) ? s[2] : c[2];
        a *= (i & 1)        ? s[3] : c[3];
        float pp = a * a;
        p[i] = pp;
        mx = fmaxf(mx, pp);
    }
    float inv = 1.0f / mx;
#pragma unroll
    for (int i = 0; i < 8; i++) g_images[b * 32 + g * 8 + i] = p[i] * inv;
}

// ------------------------------------------------------------------
__global__ void k_conv1_stats(const float* __restrict__ w1, const float* __restrict__ b1) {
    __shared__ float sh[CH2][34];
    int tid = threadIdx.x;
    int b0 = blockIdx.x * CH2;
    for (int i = tid; i < CH2 * 32; i += 128)
        sh[i >> 5][(i & 31) + 1] = g_images[(b0 + (i >> 5)) * 32 + (i & 31)];
    if (tid < CH2) { sh[tid][0] = 0.f; sh[tid][33] = 0.f; }
    __syncthreads();

    int oc = tid;
    float wA = w1[oc * 3 + 2], wB = w1[oc * 3 + 1], wC = w1[oc * 3 + 0], bb = b1[oc];
    float sum = 0.f, sq = 0.f;
    for (int r = 0; r < CH2; r++) {
#pragma unroll
        for (int p = 0; p < 32; p++) {
            float y = bb + sh[r][p] * wA + sh[r][p + 1] * wB + sh[r][p + 2] * wC;
            y = fmaxf(y, 0.f);
            sum += y;
            sq += y * y;
        }
    }
    atomicAdd(&g_stats1[oc], (double)sum);
    atomicAdd(&g_stats1[C1 + oc], (double)sq);
}

// ------------------------------------------------------------------
__global__ void k_fin1(const float* __restrict__ gamma, const float* __restrict__ beta) {
    int c = threadIdx.x;
    if (c >= C1) return;
    double N = (double)BSZ * LSP;
    double mean = g_stats1[c] / N;
    double var = g_stats1[C1 + c] / N - mean * mean;
    float a = gamma[c] * (float)(1.0 / sqrt(var + 1e-5));
    g_a1[c] = a;
    g_c1[c] = beta[c] - (float)mean * a;
}

__global__ void k_fin2(const float* __restrict__ gamma, const float* __restrict__ beta) {
    int c = threadIdx.x;
    if (c >= C2) return;
    double N = (double)BSZ * LSP;
    double mean = g_stats2[c] / N;
    double var = g_stats2[C2 + c] / N - mean * mean;
    float a = gamma[c] * (float)(1.0 / sqrt(var + 1e-5));
    g_a2[c] = a;
    g_c2[c] = beta[c] - (float)mean * a;
}

// ------------------------------------------------------------------
// conv2 via mma.sync bf16 (m16n8k16), 3-term bf16 split with SPLIT ACCUMULATORS:
//   accH += Ahi*Bhi            (chain length 1)
//   accL += Ahi*Blo; accL += Alo*Bhi   (chain length 2)
//   D = accH + accL            (alo*blo ~2^-18 dropped)
#define OFF_AH 0          // 4*34*68 = 9248 words
#define OFF_AL 9248
#define OFF_B  18496      // B region: BH 4608 + BL 4608
#define OFF_BH 18496
#define OFF_BL 23104
#define SM_FLOATS 27712   // 110848 bytes

__global__ void __launch_bounds__(256, 2)
k_conv2(const float* __restrict__ w1, const float* __restrict__ b1,
        const float* __restrict__ w2, const float* __restrict__ b2) {
    extern __shared__ float sm[];
    uint32_t* sAH = (uint32_t*)(sm + OFF_AH);
    uint32_t* sAL = (uint32_t*)(sm + OFF_AL);
    uint32_t* sBH = (uint32_t*)(sm + OFF_BH);
    uint32_t* sBL = (uint32_t*)(sm + OFF_BL);
    float* sp   = sm + OFF_B;          // overlay, used only before B staging
    float* simg = sm + OFF_B + 768;
    float* red  = sm + OFF_B;          // overlay, used only after main loop

    int tid = threadIdx.x;
    int wid = tid >> 5, lid = tid & 31;
    int g = lid >> 2, q = lid & 3;
    int bbase = blockIdx.x * 4;

    // --- stage conv1 params + images (into B-region overlay) ---
    for (int i = tid; i < 128; i += 256) {
        sp[i * 6 + 0] = w1[i * 3 + 0];
        sp[i * 6 + 1] = w1[i * 3 + 1];
        sp[i * 6 + 2] = w1[i * 3 + 2];
        sp[i * 6 + 3] = b1[i];
        sp[i * 6 + 4] = g_a1[i];
        sp[i * 6 + 5] = g_c1[i];
    }
    for (int i = tid; i < 4 * 32; i += 256) {
        int bl = i >> 5, p = i & 31;
        simg[bl * 34 + p + 1] = g_images[(bbase + bl) * 32 + p];
    }
    if (tid < 4) { simg[tid * 34] = 0.f; simg[tid * 34 + 33] = 0.f; }
    __syncthreads();

    // --- h1n = a1*relu(conv1)+c1, split to bf16 hi/lo, packed ic-pairs ---
    for (int idx = tid; idx < 4 * 34 * 64; idx += 256) {
        int bl = idx / 2176, r = idx - bl * 2176;
        int q0 = r >> 6, u = r & 63;
        float v0 = 0.f, v1 = 0.f;
        if (q0 >= 1 && q0 <= 32) {
            int p = q0 - 1;
            float i0 = simg[bl * 34 + p], i1 = simg[bl * 34 + p + 1], i2 = simg[bl * 34 + p + 2];
            const float* p0 = &sp[(2 * u) * 6];
            float y0 = p0[3] + i0 * p0[2] + i1 * p0[1] + i2 * p0[0];
            v0 = fmaf(p0[4], fmaxf(y0, 0.f), p0[5]);
            const float* p1 = &sp[(2 * u + 1) * 6];
            float y1 = p1[3] + i0 * p1[2] + i1 * p1[1] + i2 * p1[0];
            v1 = fmaf(p1[4], fmaxf(y1, 0.f), p1[5]);
        }
        int o = (bl * 34 + q0) * 68 + u;
        sAH[o] = packbf(v0, v1);
        sAL[o] = packbf(v0 - bf16f(v0), v1 - bf16f(v1));
    }

    // --- warp tile: 32 rows (batch row bl) x 32 oc ---
    int bl = wid >> 1;
    int n0 = (wid & 1) * 32;

    float accH[2][4][4], accL[2][4][4];
#pragma unroll
    for (int mt = 0; mt < 2; mt++)
#pragma unroll
        for (int j = 0; j < 4; j++)
#pragma unroll
            for (int v = 0; v < 4; v++) { accH[mt][j][v] = 0.f; accL[mt][j][v] = 0.f; }

    for (int tap = 0; tap < 3; tap++) {
        __syncthreads();
        // stage B(tap): word(kp, oc) packs ic = 2kp, 2kp+1
        for (int i = tid; i < 4096; i += 256) {
            int kp = i >> 6, oc = i & 63;
            float v0 = w2[((2 * kp) * 64 + oc) * 3 + (2 - tap)];
            float v1 = w2[((2 * kp + 1) * 64 + oc) * 3 + (2 - tap)];
            sBH[kp * 72 + oc] = packbf(v0, v1);
            sBL[kp * 72 + oc] = packbf(v0 - bf16f(v0), v1 - bf16f(v1));
        }
        __syncthreads();
#pragma unroll 2
        for (int kk = 0; kk < 8; kk++) {
            int kb2 = kk * 8;
            uint32_t AH[2][4], AL[2][4];
#pragma unroll
            for (int mt = 0; mt < 2; mt++) {
                int base = bl * 2312 + (mt * 16 + g + tap) * 68 + kb2 + q;
                AH[mt][0] = sAH[base];       AL[mt][0] = sAL[base];
                AH[mt][1] = sAH[base + 544]; AL[mt][1] = sAL[base + 544];
                AH[mt][2] = sAH[base + 4];   AL[mt][2] = sAL[base + 4];
                AH[mt][3] = sAH[base + 548]; AL[mt][3] = sAL[base + 548];
            }
            uint32_t BH[4][2], BL[4][2];
#pragma unroll
            for (int j = 0; j < 4; j++) {
                int n = n0 + 8 * j + g;
                int c0 = (kb2 + q) * 72 + n;
                int c1 = (kb2 + q + 4) * 72 + n;
                BH[j][0] = sBH[c0]; BH[j][1] = sBH[c1];
                BL[j][0] = sBL[c0]; BL[j][1] = sBL[c1];
            }
            // 8 independent HH MMAs into accH
#pragma unroll
            for (int mt = 0; mt < 2; mt++)
#pragma unroll
                for (int j = 0; j < 4; j++)
                    asm volatile(
                        "mma.sync.aligned.m16n8k16.row.col.f32.bf16.bf16.f32 "
                        "{%0,%1,%2,%3},{%4,%5,%6,%7},{%8,%9},{%0,%1,%2,%3};"
                        : "+f"(accH[mt][j][0]), "+f"(accH[mt][j][1]),
                          "+f"(accH[mt][j][2]), "+f"(accH[mt][j][3])
                        : "r"(AH[mt][0]), "r"(AH[mt][1]), "r"(AH[mt][2]), "r"(AH[mt][3]),
                          "r"(BH[j][0]), "r"(BH[j][1]));
            // 8 independent Ahi*Blo into accL
#pragma unroll
            for (int mt = 0; mt < 2; mt++)
#pragma unroll
                for (int j = 0; j < 4; j++)
                    asm volatile(
                        "mma.sync.aligned.m16n8k16.row.col.f32.bf16.bf16.f32 "
                        "{%0,%1,%2,%3},{%4,%5,%6,%7},{%8,%9},{%0,%1,%2,%3};"
                        : "+f"(accL[mt][j][0]), "+f"(accL[mt][j][1]),
                          "+f"(accL[mt][j][2]), "+f"(accL[mt][j][3])
                        : "r"(AH[mt][0]), "r"(AH[mt][1]), "r"(AH[mt][2]), "r"(AH[mt][3]),
                          "r"(BL[j][0]), "r"(BL[j][1]));
            // 8 Alo*Bhi into accL (each depends only on the matching MMA above)
#pragma unroll
            for (int mt = 0; mt < 2; mt++)
#pragma unroll
                for (int j = 0; j < 4; j++)
                    asm volatile(
                        "mma.sync.aligned.m16n8k16.row.col.f32.bf16.bf16.f32 "
                        "{%0,%1,%2,%3},{%4,%5,%6,%7},{%8,%9},{%0,%1,%2,%3};"
                        : "+f"(accL[mt][j][0]), "+f"(accL[mt][j][1]),
                          "+f"(accL[mt][j][2]), "+f"(accL[mt][j][3])
                        : "r"(AL[mt][0]), "r"(AL[mt][1]), "r"(AL[mt][2]), "r"(AL[mt][3]),
                          "r"(BH[j][0]), "r"(BH[j][1]));
        }
    }

    // --- epilogue: merge accs, bias + relu, store h2, per-oc stats ---
    __syncthreads();
    if (tid < 128) red[tid] = 0.f;
    __syncthreads();

    int b = bbase + bl;
    float bias[4][2];
#pragma unroll
    for (int j = 0; j < 4; j++) {
        bias[j][0] = __ldg(&b2[n0 + 8 * j + 2 * q]);
        bias[j][1] = __ldg(&b2[n0 + 8 * j + 2 * q + 1]);
    }
    float ssum[4][2], ssq[4][2];
#pragma unroll
    for (int j = 0; j < 4; j++)
        for (int c = 0; c < 2; c++) { ssum[j][c] = 0.f; ssq[j][c] = 0.f; }

#pragma unroll
    for (int mt = 0; mt < 2; mt++)
#pragma unroll
        for (int j = 0; j < 4; j++)
#pragma unroll
            for (int h = 0; h < 2; h++)
#pragma unroll
                for (int c = 0; c < 2; c++) {
                    int oc = n0 + 8 * j + 2 * q + c;
                    int p = mt * 16 + h * 8 + g;
                    float val = accH[mt][j][h * 2 + c] + accL[mt][j][h * 2 + c];
                    float y = fmaxf(val + bias[j][c], 0.f);
                    g_h2[(b * 64 + oc) * 32 + p] = y;
                    ssum[j][c] += y;
                    ssq[j][c]  += y * y;
                }
#pragma unroll
    for (int j = 0; j < 4; j++)
#pragma unroll
        for (int c = 0; c < 2; c++) {
#pragma unroll
            for (int mk = 4; mk <= 16; mk <<= 1) {
                ssum[j][c] += __shfl_xor_sync(0xffffffffu, ssum[j][c], mk);
                ssq[j][c]  += __shfl_xor_sync(0xffffffffu, ssq[j][c], mk);
            }
        }
    if (lid < 4) {
#pragma unroll
        for (int j = 0; j < 4; j++)
#pragma unroll
            for (int c = 0; c < 2; c++) {
                int oc = n0 + 8 * j + 2 * lid + c;
                atomicAdd(&red[oc], ssum[j][c]);
                atomicAdd(&red[64 + oc], ssq[j][c]);
            }
    }
    __syncthreads();
    if (tid < 128) atomicAdd(&g_stats2[tid], (double)red[tid]);
}

// ------------------------------------------------------------------
__global__ void k_conv3(const float* __restrict__ w3, const float* __restrict__ b3,
                        float* __restrict__ out) {
    __shared__ float sa[64], sc[64], swv[192], sb3;
    int tid = threadIdx.x;
    if (tid < 64) { sa[tid] = g_a2[tid]; sc[tid] = g_c2[tid]; }
    if (tid < 192) swv[tid] = w3[tid];
    if (tid == 0) sb3 = b3[0];
    __syncthreads();

    int t = blockIdx.x * 256 + tid;
    int b = t >> 5, p = t & 31;
    const float* base = &g_h2[b * 64 * 32];
    float acc = sb3;
#pragma unroll 4
    for (int ic = 0; ic < 64; ic++) {
        const float* row = base + ic * 32;
        float a = sa[ic], cs = sc[ic];
        float x0 = fmaf(a, row[p], cs);
        float xm = (p > 0)  ? fmaf(a, row[p - 1], cs) : 0.f;
        float xp = (p < 31) ? fmaf(a, row[p + 1], cs) : 0.f;
        acc += xm * swv[ic * 3 + 2] + x0 * swv[ic * 3 + 1] + xp * swv[ic * 3 + 0];
    }
    out[t] = tanhf(acc);
}

// ------------------------------------------------------------------
extern "C" void kernel_launch(void* const* d_in, const int* in_sizes, int n_in,
                              void* d_out, int out_size) {
    const float* x   = (const float*)d_in[0];
    const float* qp  = (const float*)d_in[1];
    const float* w1  = (const float*)d_in[2];
    const float* b1  = (const float*)d_in[3];
    const float* g1  = (const float*)d_in[4];
    const float* be1 = (const float*)d_in[5];
    const float* w2  = (const float*)d_in[6];
    const float* b2  = (const float*)d_in[7];
    const float* g2  = (const float*)d_in[8];
    const float* be2 = (const float*)d_in[9];
    const float* w3  = (const float*)d_in[10];
    const float* b3  = (const float*)d_in[11];
    float* out = (float*)d_out;

    const int smem_bytes = SM_FLOATS * (int)sizeof(float);   // 110848 B
    cudaFuncSetAttribute(k_conv2, cudaFuncAttributeMaxDynamicSharedMemorySize, smem_bytes);

    k_zero_stats<<<1, 256>>>();
    k_images<<<(BSZ * 4) / 256, 256>>>(x, qp);
    k_conv1_stats<<<BSZ / CH2, 128>>>(w1, b1);
    k_fin1<<<1, 128>>>(g1, be1);
    k_conv2<<<BSZ / 4, 256, smem_bytes>>>(w1, b1, w2, b2);
    k_fin2<<<1, 64>>>(g2, be2);
    k_conv3<<<(BSZ * 32) / 256, 256>>>(w3, b3, out);
}

// round 9
// speedup vs baseline: 2.5943x; 1.1244x over previous
#include <cuda_runtime.h>
#include <cuda_fp16.h>
#include <math.h>
#include <stdint.h>

#define BSZ   16384
#define LSP   32
#define C1    128
#define C2    64
#define CH2   16

// ---- persistent device scratch ----
__device__ float  g_images[BSZ * LSP];
__device__ float  g_h2[BSZ * C2 * LSP];
__device__ double g_stats1[2 * C1];
__device__ double g_stats2[2 * C2];
__device__ float  g_a1[C1], g_c1[C1];
__device__ float  g_a2[C2], g_c2[C2];

// pack two floats as fp16x2: low 16 bits = `even`, high = `odd`
__device__ __forceinline__ uint32_t packh(float even, float odd) {
    uint32_t r;
    asm("cvt.rn.f16x2.f32 %0, %1, %2;" : "=r"(r) : "f"(odd), "f"(even));
    return r;
}
__device__ __forceinline__ float h16f(float v) {
    return __half2float(__float2half_rn(v));
}

// ================================================================
__global__ void k_zero_stats() {
    int t = threadIdx.x;
    if (t < 2 * C1) g_stats1[t] = 0.0;
    if (t < 2 * C2) g_stats2[t] = 0.0;
}

// ------------------------------------------------------------------
// given = probs[:8]/max(probs[:8]) (sum-normalization cancels).
__global__ void k_images(const float* __restrict__ x, const float* __restrict__ qp) {
    int t = blockIdx.x * blockDim.x + threadIdx.x;
    if (t >= BSZ * 4) return;
    int b = t >> 2, g = t & 3;
    float c[4], s[4];
#pragma unroll
    for (int q = 0; q < 4; q++) {
        float th = 0.5f * (x[b * 4 + q] + qp[g * 4 + q]);
        c[q] = cosf(th);
        s[q] = sinf(th);
    }
    float p[8];
    float mx = 0.f;
#pragma unroll
    for (int i = 0; i < 8; i++) {
        float a = c[0];
        a *= ((i >> 2) & 1) ? s[1] : c[1];
        a *= ((i >> 1) & 1) ? s[2] : c[2];
        a *= (i & 1)        ? s[3] : c[3];
        float pp = a * a;
        p[i] = pp;
        mx = fmaxf(mx, pp);
    }
    float inv = 1.0f / mx;
#pragma unroll
    for (int i = 0; i < 8; i++) g_images[b * 32 + g * 8 + i] = p[i] * inv;
}

// ------------------------------------------------------------------
__global__ void k_conv1_stats(const float* __restrict__ w1, const float* __restrict__ b1) {
    __shared__ float sh[CH2][34];
    int tid = threadIdx.x;
    int b0 = blockIdx.x * CH2;
    for (int i = tid; i < CH2 * 32; i += 128)
        sh[i >> 5][(i & 31) + 1] = g_images[(b0 + (i >> 5)) * 32 + (i & 31)];
    if (tid < CH2) { sh[tid][0] = 0.f; sh[tid][33] = 0.f; }
    __syncthreads();

    int oc = tid;
    float wA = w1[oc * 3 + 2], wB = w1[oc * 3 + 1], wC = w1[oc * 3 + 0], bb = b1[oc];
    float sum = 0.f, sq = 0.f;
    for (int r = 0; r < CH2; r++) {
#pragma unroll
        for (int p = 0; p < 32; p++) {
            float y = bb + sh[r][p] * wA + sh[r][p + 1] * wB + sh[r][p + 2] * wC;
            y = fmaxf(y, 0.f);
            sum += y;
            sq += y * y;
        }
    }
    atomicAdd(&g_stats1[oc], (double)sum);
    atomicAdd(&g_stats1[C1 + oc], (double)sq);
}

// ------------------------------------------------------------------
__global__ void k_fin1(const float* __restrict__ gamma, const float* __restrict__ beta) {
    int c = threadIdx.x;
    if (c >= C1) return;
    double N = (double)BSZ * LSP;
    double mean = g_stats1[c] / N;
    double var = g_stats1[C1 + c] / N - mean * mean;
    float a = gamma[c] * (float)(1.0 / sqrt(var + 1e-5));
    g_a1[c] = a;
    g_c1[c] = beta[c] - (float)mean * a;
}

__global__ void k_fin2(const float* __restrict__ gamma, const float* __restrict__ beta) {
    int c = threadIdx.x;
    if (c >= C2) return;
    double N = (double)BSZ * LSP;
    double mean = g_stats2[c] / N;
    double var = g_stats2[C2 + c] / N - mean * mean;
    float a = gamma[c] * (float)(1.0 / sqrt(var + 1e-5));
    g_a2[c] = a;
    g_c2[c] = beta[c] - (float)mean * a;
}

// ------------------------------------------------------------------
// conv2 via mma.sync fp16 (m16n8k16), 2-term split (A exact-split, B single):
//   accH += AH*B ; accL += AL*B ; D = accH + accL
//   error ~ 2^-11 from B rounding only (A split is exact to 2^-22)
#define OFF_AH 0          // 4*34*68 = 9248 words
#define OFF_AL 9248
#define OFF_B  18496      // B region: 4608 words (fp16x2, single precision term)
#define SM_FLOATS 23104   // 92416 bytes

__global__ void __launch_bounds__(256, 2)
k_conv2(const float* __restrict__ w1, const float* __restrict__ b1,
        const float* __restrict__ w2, const float* __restrict__ b2) {
    extern __shared__ float sm[];
    uint32_t* sAH = (uint32_t*)(sm + OFF_AH);
    uint32_t* sAL = (uint32_t*)(sm + OFF_AL);
    uint32_t* sB  = (uint32_t*)(sm + OFF_B);
    float* sp   = sm + OFF_B;          // overlay, used only before B staging
    float* simg = sm + OFF_B + 768;
    float* red  = sm + OFF_B;          // overlay, used only after main loop

    int tid = threadIdx.x;
    int wid = tid >> 5, lid = tid & 31;
    int g = lid >> 2, q = lid & 3;
    int bbase = blockIdx.x * 4;

    // --- stage conv1 params + images (into B-region overlay) ---
    for (int i = tid; i < 128; i += 256) {
        sp[i * 6 + 0] = w1[i * 3 + 0];
        sp[i * 6 + 1] = w1[i * 3 + 1];
        sp[i * 6 + 2] = w1[i * 3 + 2];
        sp[i * 6 + 3] = b1[i];
        sp[i * 6 + 4] = g_a1[i];
        sp[i * 6 + 5] = g_c1[i];
    }
    for (int i = tid; i < 4 * 32; i += 256) {
        int bl = i >> 5, p = i & 31;
        simg[bl * 34 + p + 1] = g_images[(bbase + bl) * 32 + p];
    }
    if (tid < 4) { simg[tid * 34] = 0.f; simg[tid * 34 + 33] = 0.f; }
    __syncthreads();

    // --- h1n = a1*relu(conv1)+c1, exact fp16 hi/lo split, packed ic-pairs ---
    for (int idx = tid; idx < 4 * 34 * 64; idx += 256) {
        int bl = idx / 2176, r = idx - bl * 2176;
        int q0 = r >> 6, u = r & 63;
        float v0 = 0.f, v1 = 0.f;
        if (q0 >= 1 && q0 <= 32) {
            int p = q0 - 1;
            float i0 = simg[bl * 34 + p], i1 = simg[bl * 34 + p + 1], i2 = simg[bl * 34 + p + 2];
            const float* p0 = &sp[(2 * u) * 6];
            float y0 = p0[3] + i0 * p0[2] + i1 * p0[1] + i2 * p0[0];
            v0 = fmaf(p0[4], fmaxf(y0, 0.f), p0[5]);
            const float* p1 = &sp[(2 * u + 1) * 6];
            float y1 = p1[3] + i0 * p1[2] + i1 * p1[1] + i2 * p1[0];
            v1 = fmaf(p1[4], fmaxf(y1, 0.f), p1[5]);
        }
        int o = (bl * 34 + q0) * 68 + u;
        sAH[o] = packh(v0, v1);
        sAL[o] = packh(v0 - h16f(v0), v1 - h16f(v1));
    }

    // --- warp tile: 32 rows (batch row bl) x 32 oc ---
    int bl = wid >> 1;
    int n0 = (wid & 1) * 32;

    float accH[2][4][4], accL[2][4][4];
#pragma unroll
    for (int mt = 0; mt < 2; mt++)
#pragma unroll
        for (int j = 0; j < 4; j++)
#pragma unroll
            for (int v = 0; v < 4; v++) { accH[mt][j][v] = 0.f; accL[mt][j][v] = 0.f; }

    for (int tap = 0; tap < 3; tap++) {
        __syncthreads();
        // stage B(tap): word(kp, oc) packs ic = 2kp, 2kp+1
        for (int i = tid; i < 4096; i += 256) {
            int kp = i >> 6, oc = i & 63;
            float v0 = w2[((2 * kp) * 64 + oc) * 3 + (2 - tap)];
            float v1 = w2[((2 * kp + 1) * 64 + oc) * 3 + (2 - tap)];
            sB[kp * 72 + oc] = packh(v0, v1);
        }
        __syncthreads();
#pragma unroll 2
        for (int kk = 0; kk < 8; kk++) {
            int kb2 = kk * 8;
            uint32_t AH[2][4], AL[2][4];
#pragma unroll
            for (int mt = 0; mt < 2; mt++) {
                int base = bl * 2312 + (mt * 16 + g + tap) * 68 + kb2 + q;
                AH[mt][0] = sAH[base];       AL[mt][0] = sAL[base];
                AH[mt][1] = sAH[base + 544]; AL[mt][1] = sAL[base + 544];
                AH[mt][2] = sAH[base + 4];   AL[mt][2] = sAL[base + 4];
                AH[mt][3] = sAH[base + 548]; AL[mt][3] = sAL[base + 548];
            }
            uint32_t B[4][2];
#pragma unroll
            for (int j = 0; j < 4; j++) {
                int n = n0 + 8 * j + g;
                B[j][0] = sB[(kb2 + q) * 72 + n];
                B[j][1] = sB[(kb2 + q + 4) * 72 + n];
            }
            // 8 independent AH*B into accH
#pragma unroll
            for (int mt = 0; mt < 2; mt++)
#pragma unroll
                for (int j = 0; j < 4; j++)
                    asm volatile(
                        "mma.sync.aligned.m16n8k16.row.col.f32.f16.f16.f32 "
                        "{%0,%1,%2,%3},{%4,%5,%6,%7},{%8,%9},{%0,%1,%2,%3};"
                        : "+f"(accH[mt][j][0]), "+f"(accH[mt][j][1]),
                          "+f"(accH[mt][j][2]), "+f"(accH[mt][j][3])
                        : "r"(AH[mt][0]), "r"(AH[mt][1]), "r"(AH[mt][2]), "r"(AH[mt][3]),
                          "r"(B[j][0]), "r"(B[j][1]));
            // 8 independent AL*B into accL
#pragma unroll
            for (int mt = 0; mt < 2; mt++)
#pragma unroll
                for (int j = 0; j < 4; j++)
                    asm volatile(
                        "mma.sync.aligned.m16n8k16.row.col.f32.f16.f16.f32 "
                        "{%0,%1,%2,%3},{%4,%5,%6,%7},{%8,%9},{%0,%1,%2,%3};"
                        : "+f"(accL[mt][j][0]), "+f"(accL[mt][j][1]),
                          "+f"(accL[mt][j][2]), "+f"(accL[mt][j][3])
                        : "r"(AL[mt][0]), "r"(AL[mt][1]), "r"(AL[mt][2]), "r"(AL[mt][3]),
                          "r"(B[j][0]), "r"(B[j][1]));
        }
    }

    // --- epilogue: merge accs, bias + relu, store h2, per-oc stats ---
    __syncthreads();
    if (tid < 128) red[tid] = 0.f;
    __syncthreads();

    int b = bbase + bl;
    float bias[4][2];
#pragma unroll
    for (int j = 0; j < 4; j++) {
        bias[j][0] = __ldg(&b2[n0 + 8 * j + 2 * q]);
        bias[j][1] = __ldg(&b2[n0 + 8 * j + 2 * q + 1]);
    }
    float ssum[4][2], ssq[4][2];
#pragma unroll
    for (int j = 0; j < 4; j++)
        for (int c = 0; c < 2; c++) { ssum[j][c] = 0.f; ssq[j][c] = 0.f; }

#pragma unroll
    for (int mt = 0; mt < 2; mt++)
#pragma unroll
        for (int j = 0; j < 4; j++)
#pragma unroll
            for (int h = 0; h < 2; h++)
#pragma unroll
                for (int c = 0; c < 2; c++) {
                    int oc = n0 + 8 * j + 2 * q + c;
                    int p = mt * 16 + h * 8 + g;
                    float val = accH[mt][j][h * 2 + c] + accL[mt][j][h * 2 + c];
                    float y = fmaxf(val + bias[j][c], 0.f);
                    g_h2[(b * 64 + oc) * 32 + p] = y;
                    ssum[j][c] += y;
                    ssq[j][c]  += y * y;
                }
#pragma unroll
    for (int j = 0; j < 4; j++)
#pragma unroll
        for (int c = 0; c < 2; c++) {
#pragma unroll
            for (int mk = 4; mk <= 16; mk <<= 1) {
                ssum[j][c] += __shfl_xor_sync(0xffffffffu, ssum[j][c], mk);
                ssq[j][c]  += __shfl_xor_sync(0xffffffffu, ssq[j][c], mk);
            }
        }
    if (lid < 4) {
#pragma unroll
        for (int j = 0; j < 4; j++)
#pragma unroll
            for (int c = 0; c < 2; c++) {
                int oc = n0 + 8 * j + 2 * lid + c;
                atomicAdd(&red[oc], ssum[j][c]);
                atomicAdd(&red[64 + oc], ssq[j][c]);
            }
    }
    __syncthreads();
    if (tid < 128) atomicAdd(&g_stats2[tid], (double)red[tid]);
}

// ------------------------------------------------------------------
__global__ void k_conv3(const float* __restrict__ w3, const float* __restrict__ b3,
                        float* __restrict__ out) {
    __shared__ float sa[64], sc[64], swv[192], sb3;
    int tid = threadIdx.x;
    if (tid < 64) { sa[tid] = g_a2[tid]; sc[tid] = g_c2[tid]; }
    if (tid < 192) swv[tid] = w3[tid];
    if (tid == 0) sb3 = b3[0];
    __syncthreads();

    int t = blockIdx.x * 256 + tid;
    int b = t >> 5, p = t & 31;
    const float* base = &g_h2[b * 64 * 32];
    float acc = sb3;
#pragma unroll 4
    for (int ic = 0; ic < 64; ic++) {
        const float* row = base + ic * 32;
        float a = sa[ic], cs = sc[ic];
        float x0 = fmaf(a, row[p], cs);
        float xm = (p > 0)  ? fmaf(a, row[p - 1], cs) : 0.f;
        float xp = (p < 31) ? fmaf(a, row[p + 1], cs) : 0.f;
        acc += xm * swv[ic * 3 + 2] + x0 * swv[ic * 3 + 1] + xp * swv[ic * 3 + 0];
    }
    out[t] = tanhf(acc);
}

// ------------------------------------------------------------------
extern "C" void kernel_launch(void* const* d_in, const int* in_sizes, int n_in,
                              void* d_out, int out_size) {
    const float* x   = (const float*)d_in[0];
    const float* qp  = (const float*)d_in[1];
    const float* w1  = (const float*)d_in[2];
    const float* b1  = (const float*)d_in[3];
    const float* g1  = (const float*)d_in[4];
    const float* be1 = (const float*)d_in[5];
    const float* w2  = (const float*)d_in[6];
    const float* b2  = (const float*)d_in[7];
    const float* g2  = (const float*)d_in[8];
    const float* be2 = (const float*)d_in[9];
    const float* w3  = (const float*)d_in[10];
    const float* b3  = (const float*)d_in[11];
    float* out = (float*)d_out;

    const int smem_bytes = SM_FLOATS * (int)sizeof(float);   // 92416 B
    cudaFuncSetAttribute(k_conv2, cudaFuncAttributeMaxDynamicSharedMemorySize, smem_bytes);

    k_zero_stats<<<1, 256>>>();
    k_images<<<(BSZ * 4) / 256, 256>>>(x, qp);
    k_conv1_stats<<<BSZ / CH2, 128>>>(w1, b1);
    k_fin1<<<1, 128>>>(g1, be1);
    k_conv2<<<BSZ / 4, 256, smem_bytes>>>(w1, b1, w2, b2);
    k_fin2<<<1, 64>>>(g2, be2);
    k_conv3<<<(BSZ * 32) / 256, 256>>>(w3, b3, out);
}

// round 10
// speedup vs baseline: 2.9804x; 1.1488x over previous
#include <cuda_runtime.h>
#include <cuda_fp16.h>
#include <math.h>
#include <stdint.h>

#define BSZ   16384
#define LSP   32
#define C1    128
#define C2    64

// ---- persistent device scratch ----
__device__ float    g_images[BSZ * LSP];
__device__ float    g_h2[BSZ * C2 * LSP];
__device__ double   g_stats1[2 * C1];
__device__ double   g_stats2[2 * C2];
__device__ uint32_t g_w2pk[3 * 4096];     // per-tap packed fp16x2 weights [tap][kp*64+oc]

// pack two floats as fp16x2: low 16 bits = `even`, high = `odd`
__device__ __forceinline__ uint32_t packh(float even, float odd) {
    uint32_t r;
    asm("cvt.rn.f16x2.f32 %0, %1, %2;" : "=r"(r) : "f"(odd), "f"(even));
    return r;
}
__device__ __forceinline__ float h16f(float v) {
    return __half2float(__float2half_rn(v));
}

// ================================================================
// prep: zero stats + pre-pack w2 into fp16x2 per-tap layout.
__global__ void k_prep(const float* __restrict__ w2) {
    int t = threadIdx.x;
    if (t < 2 * C1) g_stats1[t] = 0.0;
    if (t < 2 * C2) g_stats2[t] = 0.0;
    for (int i = t; i < 3 * 4096; i += 256) {
        int tap = i >> 12, r = i & 4095;
        int kp = r >> 6, oc = r & 63;
        float v0 = w2[(2 * kp) * 192 + oc * 3 + (2 - tap)];
        float v1 = w2[(2 * kp + 1) * 192 + oc * 3 + (2 - tap)];
        g_w2pk[i] = packh(v0, v1);
    }
}

// ------------------------------------------------------------------
// images (given = probs[:8]/max — sum-normalization cancels) + conv1 stats.
// Block: 256 threads, 64 batch rows.
__global__ void k_imgstats(const float* __restrict__ x, const float* __restrict__ qp,
                           const float* __restrict__ w1, const float* __restrict__ b1) {
    __shared__ float sh[64][34];
    int tid = threadIdx.x;
    int b0 = blockIdx.x * 64;

    // phase A: one patch per thread
    {
        int r = tid >> 2, g = tid & 3;
        int b = b0 + r;
        float c[4], s[4];
#pragma unroll
        for (int q = 0; q < 4; q++) {
            float th = 0.5f * (x[b * 4 + q] + qp[g * 4 + q]);
            c[q] = cosf(th);
            s[q] = sinf(th);
        }
        float p[8];
        float mx = 0.f;
#pragma unroll
        for (int i = 0; i < 8; i++) {
            float a = c[0];
            a *= ((i >> 2) & 1) ? s[1] : c[1];
            a *= ((i >> 1) & 1) ? s[2] : c[2];
            a *= (i & 1)        ? s[3] : c[3];
            float pp = a * a;
            p[i] = pp;
            mx = fmaxf(mx, pp);
        }
        float inv = 1.0f / mx;
#pragma unroll
        for (int i = 0; i < 8; i++) {
            float v = p[i] * inv;
            sh[r][g * 8 + i + 1] = v;
            g_images[b * 32 + g * 8 + i] = v;
        }
        if (g == 0) sh[r][0] = 0.f;
        if (g == 3) sh[r][33] = 0.f;
    }
    __syncthreads();

    // phase B: conv1+relu stats; thread = (oc, row-half)
    {
        int oc = tid & 127, half = tid >> 7;
        float wA = w1[oc * 3 + 2], wB = w1[oc * 3 + 1], wC = w1[oc * 3 + 0], bb = b1[oc];
        float sum = 0.f, sq = 0.f;
        for (int rr = 0; rr < 32; rr++) {
            const float* row = sh[half * 32 + rr];
#pragma unroll
            for (int p = 0; p < 32; p++) {
                float y = bb + row[p] * wA + row[p + 1] * wB + row[p + 2] * wC;
                y = fmaxf(y, 0.f);
                sum += y;
                sq += y * y;
            }
        }
        atomicAdd(&g_stats1[oc], (double)sum);
        atomicAdd(&g_stats1[C1 + oc], (double)sq);
    }
}

// ------------------------------------------------------------------
// conv2 via mma.sync fp16 (m16n8k16), 2-term split (A exact hi/lo, B single):
//   accH += AH*B ; accL += AL*B ; D = accH + accL
// Double-buffered B, fin1 folded into prologue.
#define OFF_AH 0          // 4*34*68 = 9248 words
#define OFF_AL 9248
#define OFF_B0 18496      // 4608 words
#define OFF_B1 23104      // 4608 words
#define SM_FLOATS 27712   // 110848 bytes

__global__ void __launch_bounds__(256, 2)
k_conv2(const float* __restrict__ w1, const float* __restrict__ b1,
        const float* __restrict__ g1, const float* __restrict__ be1,
        const float* __restrict__ b2) {
    extern __shared__ float sm[];
    uint32_t* sAH = (uint32_t*)(sm + OFF_AH);
    uint32_t* sAL = (uint32_t*)(sm + OFF_AL);
    uint32_t* sB0 = (uint32_t*)(sm + OFF_B0);
    uint32_t* sB1 = (uint32_t*)(sm + OFF_B1);
    float* sp   = sm + OFF_B1;         // overlay: prologue only (before B1 staging)
    float* simg = sm + OFF_B1 + 768;
    float* red  = sm + OFF_B1;         // overlay: epilogue only (after tap1 done)

    int tid = threadIdx.x;
    int wid = tid >> 5, lid = tid & 31;
    int g = lid >> 2, q = lid & 3;
    int bbase = blockIdx.x * 4;

    // --- phase 0: conv1 params + fin1 + images ---
    for (int i = tid; i < 128; i += 256) {
        sp[i * 6 + 0] = w1[i * 3 + 0];
        sp[i * 6 + 1] = w1[i * 3 + 1];
        sp[i * 6 + 2] = w1[i * 3 + 2];
        sp[i * 6 + 3] = b1[i];
        double N = 524288.0;
        double mean = g_stats1[i] / N;
        double var = g_stats1[C1 + i] / N - mean * mean;
        float a = g1[i] * (float)(1.0 / sqrt(var + 1e-5));
        sp[i * 6 + 4] = a;
        sp[i * 6 + 5] = be1[i] - (float)mean * a;
    }
    for (int i = tid; i < 4 * 32; i += 256) {
        int bl = i >> 5, p = i & 31;
        simg[bl * 34 + p + 1] = g_images[(bbase + bl) * 32 + p];
    }
    if (tid < 4) { simg[tid * 34] = 0.f; simg[tid * 34 + 33] = 0.f; }
    __syncthreads();

    // --- phase 1: h1n exact fp16 hi/lo split + stage B(tap0)->B0 ---
    for (int idx = tid; idx < 4 * 34 * 64; idx += 256) {
        int bl = idx / 2176, r = idx - bl * 2176;
        int q0 = r >> 6, u = r & 63;
        float v0 = 0.f, v1 = 0.f;
        if (q0 >= 1 && q0 <= 32) {
            int p = q0 - 1;
            float i0 = simg[bl * 34 + p], i1 = simg[bl * 34 + p + 1], i2 = simg[bl * 34 + p + 2];
            const float* p0 = &sp[(2 * u) * 6];
            float y0 = p0[3] + i0 * p0[2] + i1 * p0[1] + i2 * p0[0];
            v0 = fmaf(p0[4], fmaxf(y0, 0.f), p0[5]);
            const float* p1 = &sp[(2 * u + 1) * 6];
            float y1 = p1[3] + i0 * p1[2] + i1 * p1[1] + i2 * p1[0];
            v1 = fmaf(p1[4], fmaxf(y1, 0.f), p1[5]);
        }
        int o = (bl * 34 + q0) * 68 + u;
        sAH[o] = packh(v0, v1);
        sAL[o] = packh(v0 - h16f(v0), v1 - h16f(v1));
    }
    {   // vectorized B stage: tap0 -> B0
        const uint4* src = (const uint4*)g_w2pk;
#pragma unroll
        for (int i = tid; i < 1024; i += 256) {
            int kp = i >> 4, oc4 = (i & 15) * 4;
            *(uint4*)(sB0 + kp * 72 + oc4) = src[i];
        }
    }
    __syncthreads();

    // --- main: warp tile 32 rows (batch row bl) x 32 oc ---
    int bl = wid >> 1;
    int n0 = (wid & 1) * 32;

    float accH[2][4][4], accL[2][4][4];
#pragma unroll
    for (int mt = 0; mt < 2; mt++)
#pragma unroll
        for (int j = 0; j < 4; j++)
#pragma unroll
            for (int v = 0; v < 4; v++) { accH[mt][j][v] = 0.f; accL[mt][j][v] = 0.f; }

#define MMA_TAP(tap, SB) do { \
    _Pragma("unroll 2") \
    for (int kk = 0; kk < 8; kk++) { \
        int kb2 = kk * 8; \
        uint32_t AH[2][4], AL[2][4]; \
        _Pragma("unroll") \
        for (int mt = 0; mt < 2; mt++) { \
            int base = bl * 2312 + (mt * 16 + g + (tap)) * 68 + kb2 + q; \
            AH[mt][0] = sAH[base];       AL[mt][0] = sAL[base]; \
            AH[mt][1] = sAH[base + 544]; AL[mt][1] = sAL[base + 544]; \
            AH[mt][2] = sAH[base + 4];   AL[mt][2] = sAL[base + 4]; \
            AH[mt][3] = sAH[base + 548]; AL[mt][3] = sAL[base + 548]; \
        } \
        uint32_t B[4][2]; \
        _Pragma("unroll") \
        for (int j = 0; j < 4; j++) { \
            int n = n0 + 8 * j + g; \
            B[j][0] = (SB)[(kb2 + q) * 72 + n]; \
            B[j][1] = (SB)[(kb2 + q + 4) * 72 + n]; \
        } \
        _Pragma("unroll") \
        for (int mt = 0; mt < 2; mt++) \
            _Pragma("unroll") \
            for (int j = 0; j < 4; j++) \
                asm volatile( \
                    "mma.sync.aligned.m16n8k16.row.col.f32.f16.f16.f32 " \
                    "{%0,%1,%2,%3},{%4,%5,%6,%7},{%8,%9},{%0,%1,%2,%3};" \
                    : "+f"(accH[mt][j][0]), "+f"(accH[mt][j][1]), \
                      "+f"(accH[mt][j][2]), "+f"(accH[mt][j][3]) \
                    : "r"(AH[mt][0]), "r"(AH[mt][1]), "r"(AH[mt][2]), "r"(AH[mt][3]), \
                      "r"(B[j][0]), "r"(B[j][1])); \
        _Pragma("unroll") \
        for (int mt = 0; mt < 2; mt++) \
            _Pragma("unroll") \
            for (int j = 0; j < 4; j++) \
                asm volatile( \
                    "mma.sync.aligned.m16n8k16.row.col.f32.f16.f16.f32 " \
                    "{%0,%1,%2,%3},{%4,%5,%6,%7},{%8,%9},{%0,%1,%2,%3};" \
                    : "+f"(accL[mt][j][0]), "+f"(accL[mt][j][1]), \
                      "+f"(accL[mt][j][2]), "+f"(accL[mt][j][3]) \
                    : "r"(AL[mt][0]), "r"(AL[mt][1]), "r"(AL[mt][2]), "r"(AL[mt][3]), \
                      "r"(B[j][0]), "r"(B[j][1])); \
    } } while (0)

#define STAGE_B(tap, SB) do { \
    const uint4* src = (const uint4*)(g_w2pk + (tap) * 4096); \
    _Pragma("unroll") \
    for (int i = tid; i < 1024; i += 256) { \
        int kp = i >> 4, oc4 = (i & 15) * 4; \
        *(uint4*)((SB) + kp * 72 + oc4) = src[i]; \
    } } while (0)

    STAGE_B(1, sB1);          // overwrites sp/simg (prologue done)
    MMA_TAP(0, sB0);
    __syncthreads();          // publish B1; all done with B0
    STAGE_B(2, sB0);
    MMA_TAP(1, sB1);
    __syncthreads();          // publish B0(tap2)
    MMA_TAP(2, sB0);

    // --- epilogue: merge accs, bias + relu, store h2, per-oc stats ---
    __syncthreads();
    if (tid < 128) red[tid] = 0.f;
    __syncthreads();

    int b = bbase + bl;
    float bias[4][2];
#pragma unroll
    for (int j = 0; j < 4; j++) {
        bias[j][0] = __ldg(&b2[n0 + 8 * j + 2 * q]);
        bias[j][1] = __ldg(&b2[n0 + 8 * j + 2 * q + 1]);
    }
    float ssum[4][2], ssq[4][2];
#pragma unroll
    for (int j = 0; j < 4; j++)
        for (int c = 0; c < 2; c++) { ssum[j][c] = 0.f; ssq[j][c] = 0.f; }

#pragma unroll
    for (int mt = 0; mt < 2; mt++)
#pragma unroll
        for (int j = 0; j < 4; j++)
#pragma unroll
            for (int h = 0; h < 2; h++)
#pragma unroll
                for (int c = 0; c < 2; c++) {
                    int oc = n0 + 8 * j + 2 * q + c;
                    int p = mt * 16 + h * 8 + g;
                    float val = accH[mt][j][h * 2 + c] + accL[mt][j][h * 2 + c];
                    float y = fmaxf(val + bias[j][c], 0.f);
                    g_h2[(b * 64 + oc) * 32 + p] = y;
                    ssum[j][c] += y;
                    ssq[j][c]  += y * y;
                }
#pragma unroll
    for (int j = 0; j < 4; j++)
#pragma unroll
        for (int c = 0; c < 2; c++) {
#pragma unroll
            for (int mk = 4; mk <= 16; mk <<= 1) {
                ssum[j][c] += __shfl_xor_sync(0xffffffffu, ssum[j][c], mk);
                ssq[j][c]  += __shfl_xor_sync(0xffffffffu, ssq[j][c], mk);
            }
        }
    if (lid < 4) {
#pragma unroll
        for (int j = 0; j < 4; j++)
#pragma unroll
            for (int c = 0; c < 2; c++) {
                int oc = n0 + 8 * j + 2 * lid + c;
                atomicAdd(&red[oc], ssum[j][c]);
                atomicAdd(&red[64 + oc], ssq[j][c]);
            }
    }
    __syncthreads();
    if (tid < 128) atomicAdd(&g_stats2[tid], (double)red[tid]);
}

// ------------------------------------------------------------------
// fin2 (folded) + BN2 affine + conv3 + tanh.
__global__ void k_conv3(const float* __restrict__ g2, const float* __restrict__ be2,
                        const float* __restrict__ w3, const float* __restrict__ b3,
                        float* __restrict__ out) {
    __shared__ float sa[64], sc[64], swv[192], sb3;
    int tid = threadIdx.x;
    if (tid < 64) {
        double N = 524288.0;
        double mean = g_stats2[tid] / N;
        double var = g_stats2[C2 + tid] / N - mean * mean;
        float a = g2[tid] * (float)(1.0 / sqrt(var + 1e-5));
        sa[tid] = a;
        sc[tid] = be2[tid] - (float)mean * a;
    }
    if (tid < 192) swv[tid] = w3[tid];
    if (tid == 0) sb3 = b3[0];
    __syncthreads();

    int t = blockIdx.x * 256 + tid;
    int b = t >> 5, p = t & 31;
    const float* base = &g_h2[b * 64 * 32];
    float acc = sb3;
#pragma unroll 4
    for (int ic = 0; ic < 64; ic++) {
        const float* row = base + ic * 32;
        float a = sa[ic], cs = sc[ic];
        float x0 = fmaf(a, row[p], cs);
        float xm = (p > 0)  ? fmaf(a, row[p - 1], cs) : 0.f;
        float xp = (p < 31) ? fmaf(a, row[p + 1], cs) : 0.f;
        acc += xm * swv[ic * 3 + 2] + x0 * swv[ic * 3 + 1] + xp * swv[ic * 3 + 0];
    }
    out[t] = tanhf(acc);
}

// ------------------------------------------------------------------
extern "C" void kernel_launch(void* const* d_in, const int* in_sizes, int n_in,
                              void* d_out, int out_size) {
    const float* x   = (const float*)d_in[0];
    const float* qp  = (const float*)d_in[1];
    const float* w1  = (const float*)d_in[2];
    const float* b1  = (const float*)d_in[3];
    const float* g1  = (const float*)d_in[4];
    const float* be1 = (const float*)d_in[5];
    const float* w2  = (const float*)d_in[6];
    const float* b2  = (const float*)d_in[7];
    const float* g2  = (const float*)d_in[8];
    const float* be2 = (const float*)d_in[9];
    const float* w3  = (const float*)d_in[10];
    const float* b3  = (const float*)d_in[11];
    float* out = (float*)d_out;

    const int smem_bytes = SM_FLOATS * (int)sizeof(float);   // 110848 B
    cudaFuncSetAttribute(k_conv2, cudaFuncAttributeMaxDynamicSharedMemorySize, smem_bytes);

    k_prep<<<1, 256>>>(w2);
    k_imgstats<<<BSZ / 64, 256>>>(x, qp, w1, b1);
    k_conv2<<<BSZ / 4, 256, smem_bytes>>>(w1, b1, g1, be1, b2);
    k_conv3<<<(BSZ * 32) / 256, 256>>>(g2, be2, w3, b3, out);
}

// round 14
// speedup vs baseline: 3.0163x; 1.0120x over previous
#include <cuda_runtime.h>
#include <cuda_fp16.h>
#include <math.h>
#include <stdint.h>

#define BSZ   16384
#define LSP   32
#define C1    128
#define C2    64

// ---- persistent device scratch ----
__device__ float    g_images[BSZ * LSP];
__device__ float    g_h2f[BSZ * LSP * 64];   // h2 fp32, layout [b][p][oc]  (134 MB)
__device__ double   g_stats1[2 * C1];
__device__ double   g_stats2[2 * C2];
__device__ uint32_t g_w2pk[3 * 4096];        // per-tap packed fp16x2 weights [tap][kp*64+oc]

// pack two floats as fp16x2: low 16 bits = `even`, high = `odd`
__device__ __forceinline__ uint32_t packh(float even, float odd) {
    uint32_t r;
    asm("cvt.rn.f16x2.f32 %0, %1, %2;" : "=r"(r) : "f"(odd), "f"(even));
    return r;
}
__device__ __forceinline__ float h16f(float v) {
    return __half2float(__float2half_rn(v));
}

// ================================================================
// prep: zero stats + pre-pack w2 into fp16x2 per-tap layout.
__global__ void k_prep(const float* __restrict__ w2) {
    int t = threadIdx.x;
    if (t < 2 * C1) g_stats1[t] = 0.0;
    if (t < 2 * C2) g_stats2[t] = 0.0;
    for (int i = t; i < 3 * 4096; i += 256) {
        int tap = i >> 12, r = i & 4095;
        int kp = r >> 6, oc = r & 63;
        float v0 = w2[(2 * kp) * 192 + oc * 3 + (2 - tap)];
        float v1 = w2[(2 * kp + 1) * 192 + oc * 3 + (2 - tap)];
        g_w2pk[i] = packh(v0, v1);
    }
}

// ------------------------------------------------------------------
// images (given = probs[:8]/max — sum-normalization cancels) + conv1 stats.
__global__ void k_imgstats(const float* __restrict__ x, const float* __restrict__ qp,
                           const float* __restrict__ w1, const float* __restrict__ b1) {
    __shared__ float sh[64][34];
    int tid = threadIdx.x;
    int b0 = blockIdx.x * 64;

    {   // phase A: one patch per thread
        int r = tid >> 2, g = tid & 3;
        int b = b0 + r;
        float c[4], s[4];
#pragma unroll
        for (int q = 0; q < 4; q++) {
            float th = 0.5f * (x[b * 4 + q] + qp[g * 4 + q]);
            c[q] = cosf(th);
            s[q] = sinf(th);
        }
        float p[8];
        float mx = 0.f;
#pragma unroll
        for (int i = 0; i < 8; i++) {
            float a = c[0];
            a *= ((i >> 2) & 1) ? s[1] : c[1];
            a *= ((i >> 1) & 1) ? s[2] : c[2];
            a *= (i & 1)        ? s[3] : c[3];
            float pp = a * a;
            p[i] = pp;
            mx = fmaxf(mx, pp);
        }
        float inv = 1.0f / mx;
#pragma unroll
        for (int i = 0; i < 8; i++) {
            float v = p[i] * inv;
            sh[r][g * 8 + i + 1] = v;
            g_images[b * 32 + g * 8 + i] = v;
        }
        if (g == 0) sh[r][0] = 0.f;
        if (g == 3) sh[r][33] = 0.f;
    }
    __syncthreads();

    {   // phase B: conv1+relu stats; thread = (oc, row-half)
        int oc = tid & 127, half = tid >> 7;
        float wA = w1[oc * 3 + 2], wB = w1[oc * 3 + 1], wC = w1[oc * 3 + 0], bb = b1[oc];
        float sum = 0.f, sq = 0.f;
        for (int rr = 0; rr < 32; rr++) {
            const float* row = sh[half * 32 + rr];
#pragma unroll
            for (int p = 0; p < 32; p++) {
                float y = bb + row[p] * wA + row[p + 1] * wB + row[p + 2] * wC;
                y = fmaxf(y, 0.f);
                sum += y;
                sq += y * y;
            }
        }
        atomicAdd(&g_stats1[oc], (double)sum);
        atomicAdd(&g_stats1[C1 + oc], (double)sq);
    }
}

// ------------------------------------------------------------------
// conv2 via mma.sync fp16 (m16n8k16), 2-term split (A exact hi/lo, B single).
#define OFF_AH 0          // 4*34*68 = 9248 words
#define OFF_AL 9248
#define OFF_B0 18496      // 4608 words
#define OFF_B1 23104      // 4608 words
#define SM_FLOATS 27712   // 110848 bytes

__global__ void __launch_bounds__(256, 2)
k_conv2(const float* __restrict__ w1, const float* __restrict__ b1,
        const float* __restrict__ g1, const float* __restrict__ be1,
        const float* __restrict__ b2) {
    extern __shared__ float sm[];
    uint32_t* sAH = (uint32_t*)(sm + OFF_AH);
    uint32_t* sAL = (uint32_t*)(sm + OFF_AL);
    uint32_t* sB0 = (uint32_t*)(sm + OFF_B0);
    uint32_t* sB1 = (uint32_t*)(sm + OFF_B1);
    float* sp   = sm + OFF_B1;         // overlay: prologue only
    float* simg = sm + OFF_B1 + 768;
    float* red  = sm + OFF_B1;         // overlay: epilogue only

    int tid = threadIdx.x;
    int wid = tid >> 5, lid = tid & 31;
    int g = lid >> 2, q = lid & 3;
    int bbase = blockIdx.x * 4;

    // --- phase 0: conv1 params + fin1 + images ---
    for (int i = tid; i < 128; i += 256) {
        sp[i * 6 + 0] = w1[i * 3 + 0];
        sp[i * 6 + 1] = w1[i * 3 + 1];
        sp[i * 6 + 2] = w1[i * 3 + 2];
        sp[i * 6 + 3] = b1[i];
        double N = 524288.0;
        double mean = g_stats1[i] / N;
        double var = g_stats1[C1 + i] / N - mean * mean;
        float a = g1[i] * (float)(1.0 / sqrt(var + 1e-5));
        sp[i * 6 + 4] = a;
        sp[i * 6 + 5] = be1[i] - (float)mean * a;
    }
    for (int i = tid; i < 4 * 32; i += 256) {
        int bl = i >> 5, p = i & 31;
        simg[bl * 34 + p + 1] = g_images[(bbase + bl) * 32 + p];
    }
    if (tid < 4) { simg[tid * 34] = 0.f; simg[tid * 34 + 33] = 0.f; }
    __syncthreads();

    // --- phase 1: h1n exact fp16 hi/lo split + stage B(tap0)->B0 ---
    for (int idx = tid; idx < 4 * 34 * 64; idx += 256) {
        int bl = idx / 2176, r = idx - bl * 2176;
        int q0 = r >> 6, u = r & 63;
        float v0 = 0.f, v1 = 0.f;
        if (q0 >= 1 && q0 <= 32) {
            int p = q0 - 1;
            float i0 = simg[bl * 34 + p], i1 = simg[bl * 34 + p + 1], i2 = simg[bl * 34 + p + 2];
            const float* p0 = &sp[(2 * u) * 6];
            float y0 = p0[3] + i0 * p0[2] + i1 * p0[1] + i2 * p0[0];
            v0 = fmaf(p0[4], fmaxf(y0, 0.f), p0[5]);
            const float* p1 = &sp[(2 * u + 1) * 6];
            float y1 = p1[3] + i0 * p1[2] + i1 * p1[1] + i2 * p1[0];
            v1 = fmaf(p1[4], fmaxf(y1, 0.f), p1[5]);
        }
        int o = (bl * 34 + q0) * 68 + u;
        sAH[o] = packh(v0, v1);
        sAL[o] = packh(v0 - h16f(v0), v1 - h16f(v1));
    }
    {   // vectorized B stage: tap0 -> B0
        const uint4* src = (const uint4*)g_w2pk;
#pragma unroll
        for (int i = tid; i < 1024; i += 256) {
            int kp = i >> 4, oc4 = (i & 15) * 4;
            *(uint4*)(sB0 + kp * 72 + oc4) = src[i];
        }
    }
    __syncthreads();

    // --- main: warp tile 32 rows (batch row bl) x 32 oc ---
    int bl = wid >> 1;
    int n0 = (wid & 1) * 32;

    float accH[2][4][4], accL[2][4][4];
#pragma unroll
    for (int mt = 0; mt < 2; mt++)
#pragma unroll
        for (int j = 0; j < 4; j++)
#pragma unroll
            for (int v = 0; v < 4; v++) { accH[mt][j][v] = 0.f; accL[mt][j][v] = 0.f; }

#define MMA_TAP(tap, SB) do { \
    _Pragma("unroll 2") \
    for (int kk = 0; kk < 8; kk++) { \
        int kb2 = kk * 8; \
        uint32_t AH[2][4], AL[2][4]; \
        _Pragma("unroll") \
        for (int mt = 0; mt < 2; mt++) { \
            int base = bl * 2312 + (mt * 16 + g + (tap)) * 68 + kb2 + q; \
            AH[mt][0] = sAH[base];       AL[mt][0] = sAL[base]; \
            AH[mt][1] = sAH[base + 544]; AL[mt][1] = sAL[base + 544]; \
            AH[mt][2] = sAH[base + 4];   AL[mt][2] = sAL[base + 4]; \
            AH[mt][3] = sAH[base + 548]; AL[mt][3] = sAL[base + 548]; \
        } \
        uint32_t B[4][2]; \
        _Pragma("unroll") \
        for (int j = 0; j < 4; j++) { \
            int n = n0 + 8 * j + g; \
            B[j][0] = (SB)[(kb2 + q) * 72 + n]; \
            B[j][1] = (SB)[(kb2 + q + 4) * 72 + n]; \
        } \
        _Pragma("unroll") \
        for (int mt = 0; mt < 2; mt++) \
            _Pragma("unroll") \
            for (int j = 0; j < 4; j++) \
                asm volatile( \
                    "mma.sync.aligned.m16n8k16.row.col.f32.f16.f16.f32 " \
                    "{%0,%1,%2,%3},{%4,%5,%6,%7},{%8,%9},{%0,%1,%2,%3};" \
                    : "+f"(accH[mt][j][0]), "+f"(accH[mt][j][1]), \
                      "+f"(accH[mt][j][2]), "+f"(accH[mt][j][3]) \
                    : "r"(AH[mt][0]), "r"(AH[mt][1]), "r"(AH[mt][2]), "r"(AH[mt][3]), \
                      "r"(B[j][0]), "r"(B[j][1])); \
        _Pragma("unroll") \
        for (int mt = 0; mt < 2; mt++) \
            _Pragma("unroll") \
            for (int j = 0; j < 4; j++) \
                asm volatile( \
                    "mma.sync.aligned.m16n8k16.row.col.f32.f16.f16.f32 " \
                    "{%0,%1,%2,%3},{%4,%5,%6,%7},{%8,%9},{%0,%1,%2,%3};" \
                    : "+f"(accL[mt][j][0]), "+f"(accL[mt][j][1]), \
                      "+f"(accL[mt][j][2]), "+f"(accL[mt][j][3]) \
                    : "r"(AL[mt][0]), "r"(AL[mt][1]), "r"(AL[mt][2]), "r"(AL[mt][3]), \
                      "r"(B[j][0]), "r"(B[j][1])); \
    } } while (0)

#define STAGE_B(tap, SB) do { \
    const uint4* src = (const uint4*)(g_w2pk + (tap) * 4096); \
    _Pragma("unroll") \
    for (int i = tid; i < 1024; i += 256) { \
        int kp = i >> 4, oc4 = (i & 15) * 4; \
        *(uint4*)((SB) + kp * 72 + oc4) = src[i]; \
    } } while (0)

    STAGE_B(1, sB1);
    MMA_TAP(0, sB0);
    __syncthreads();
    STAGE_B(2, sB0);
    MMA_TAP(1, sB1);
    __syncthreads();
    MMA_TAP(2, sB0);

    // --- epilogue: merge, bias+relu, store fp32 h2 [b][p][oc] via float2, stats ---
    __syncthreads();
    if (tid < 128) red[tid] = 0.f;
    __syncthreads();

    int b = bbase + bl;
    float bias[4][2];
#pragma unroll
    for (int j = 0; j < 4; j++) {
        bias[j][0] = __ldg(&b2[n0 + 8 * j + 2 * q]);
        bias[j][1] = __ldg(&b2[n0 + 8 * j + 2 * q + 1]);
    }
    float ssum[4][2], ssq[4][2];
#pragma unroll
    for (int j = 0; j < 4; j++)
        for (int c = 0; c < 2; c++) { ssum[j][c] = 0.f; ssq[j][c] = 0.f; }

    float2* h2v = (float2*)g_h2f;
#pragma unroll
    for (int mt = 0; mt < 2; mt++)
#pragma unroll
        for (int j = 0; j < 4; j++)
#pragma unroll
            for (int h = 0; h < 2; h++) {
                int p = mt * 16 + h * 8 + g;
                float y0 = fmaxf(accH[mt][j][h * 2 + 0] + accL[mt][j][h * 2 + 0] + bias[j][0], 0.f);
                float y1 = fmaxf(accH[mt][j][h * 2 + 1] + accL[mt][j][h * 2 + 1] + bias[j][1], 0.f);
                h2v[(b * 32 + p) * 32 + (n0 + 8 * j) / 2 + q] = make_float2(y0, y1);
                ssum[j][0] += y0; ssq[j][0] += y0 * y0;
                ssum[j][1] += y1; ssq[j][1] += y1 * y1;
            }
#pragma unroll
    for (int j = 0; j < 4; j++)
#pragma unroll
        for (int c = 0; c < 2; c++) {
#pragma unroll
            for (int mk = 4; mk <= 16; mk <<= 1) {
                ssum[j][c] += __shfl_xor_sync(0xffffffffu, ssum[j][c], mk);
                ssq[j][c]  += __shfl_xor_sync(0xffffffffu, ssq[j][c], mk);
            }
        }
    if (lid < 4) {
#pragma unroll
        for (int j = 0; j < 4; j++)
#pragma unroll
            for (int c = 0; c < 2; c++) {
                int oc = n0 + 8 * j + 2 * lid + c;
                atomicAdd(&red[oc], ssum[j][c]);
                atomicAdd(&red[64 + oc], ssq[j][c]);
            }
    }
    __syncthreads();
    if (tid < 128) atomicAdd(&g_stats2[tid], (double)red[tid]);
}

// ------------------------------------------------------------------
// conv3: fin2 folded, BN folded into w3a = w3*a2 + position-gated S constants,
// fp32 h2 [b][p][oc] staged in smem (row stride 76 -> conflict-free LDS.128).
// Block: 128 threads = 4 batch rows x 32 positions.
__global__ void __launch_bounds__(128)
k_conv3(const float* __restrict__ g2, const float* __restrict__ be2,
        const float* __restrict__ w3, const float* __restrict__ b3,
        float* __restrict__ out) {
    __shared__ float sh2[4 * 34 * 76];      // halo rows (p=-1, p=32) zeroed
    __shared__ float sw3a[192];
    __shared__ float sac[128];              // a2[64], c2[64]
    __shared__ float sS[3];

    int tid = threadIdx.x;
    if (tid < 64) {
        double N = 524288.0;
        double mean = g_stats2[tid] / N;
        double var = g_stats2[C2 + tid] / N - mean * mean;
        float a = g2[tid] * (float)(1.0 / sqrt(var + 1e-5));
        sac[tid] = a;
        sac[64 + tid] = be2[tid] - (float)mean * a;
    }
    // zero halo rows: 4 b x 2 rows x 76 words
    for (int i = tid; i < 608; i += 128) {
        int b = i / 152, r = (i / 76) & 1, w = i % 76;
        sh2[(b * 34 + (r ? 33 : 0)) * 76 + w] = 0.f;
    }
    __syncthreads();
    if (tid < 64) {
        float a = sac[tid];
        sw3a[tid * 3 + 0] = w3[tid * 3 + 0] * a;
        sw3a[tid * 3 + 1] = w3[tid * 3 + 1] * a;
        sw3a[tid * 3 + 2] = w3[tid * 3 + 2] * a;
    }
    if (tid < 3) {
        float s = 0.f;
        for (int ic = 0; ic < 64; ic++) s += w3[ic * 3 + tid] * sac[64 + ic];
        sS[tid] = s;
    }
    // stage 4 rows of h2: 2048 uint4, fully coalesced
    {
        const uint4* src = (const uint4*)g_h2f + (size_t)blockIdx.x * 2048;
        for (int i = tid; i < 2048; i += 128) {
            int b = i >> 9, r = (i >> 4) & 31, c = i & 15;
            *(uint4*)(sh2 + (b * 34 + r + 1) * 76 + c * 4) = src[i];
        }
    }
    __syncthreads();

    int b = tid >> 5, p = tid & 31;
    const float* base = sh2 + b * 34 * 76;
    const float* r0 = base + p * 76;            // h2[p-1] (halo at p=0)
    const float* r1 = base + (p + 1) * 76;      // h2[p]
    const float* r2 = base + (p + 2) * 76;      // h2[p+1] (halo at p=31)

    float acc = b3[0] + sS[1] + (p > 0 ? sS[2] : 0.f) + (p < 31 ? sS[0] : 0.f);
#pragma unroll
    for (int i = 0; i < 16; i++) {
        float4 xm = *(const float4*)(r0 + i * 4);
        float4 x0 = *(const float4*)(r1 + i * 4);
        float4 xp = *(const float4*)(r2 + i * 4);
        const float* w0 = &sw3a[i * 12];
        acc += xm.x * w0[2]  + x0.x * w0[1]  + xp.x * w0[0];
        acc += xm.y * w0[5]  + x0.y * w0[4]  + xp.y * w0[3];
        acc += xm.z * w0[8]  + x0.z * w0[7]  + xp.z * w0[6];
        acc += xm.w * w0[11] + x0.w * w0[10] + xp.w * w0[9];
    }
    out[(size_t)(blockIdx.x * 4 + b) * 32 + p] = tanhf(acc);
}

// ------------------------------------------------------------------
extern "C" void kernel_launch(void* const* d_in, const int* in_sizes, int n_in,
                              void* d_out, int out_size) {
    const float* x   = (const float*)d_in[0];
    const float* qp  = (const float*)d_in[1];
    const float* w1  = (const float*)d_in[2];
    const float* b1  = (const float*)d_in[3];
    const float* g1  = (const float*)d_in[4];
    const float* be1 = (const float*)d_in[5];
    const float* w2  = (const float*)d_in[6];
    const float* b2  = (const float*)d_in[7];
    const float* g2  = (const float*)d_in[8];
    const float* be2 = (const float*)d_in[9];
    const float* w3  = (const float*)d_in[10];
    const float* b3  = (const float*)d_in[11];
    float* out = (float*)d_out;

    const int smem_bytes = SM_FLOATS * (int)sizeof(float);   // 110848 B
    cudaFuncSetAttribute(k_conv2, cudaFuncAttributeMaxDynamicSharedMemorySize, smem_bytes);

    k_prep<<<1, 256>>>(w2);
    k_imgstats<<<BSZ / 64, 256>>>(x, qp, w1, b1);
    k_conv2<<<BSZ / 4, 256, smem_bytes>>>(w1, b1, g1, be1, b2);
    k_conv3<<<BSZ / 4, 128>>>(g2, be2, w3, b3, out);
}

// round 15
// speedup vs baseline: 3.0346x; 1.0061x over previous
#include <cuda_runtime.h>
#include <cuda_fp16.h>
#include <math.h>
#include <stdint.h>

#define BSZ   16384
#define LSP   32
#define C1    128
#define C2    64

// ---- persistent device scratch ----
__device__ float    g_images[BSZ * LSP];
__device__ float    g_h2f[BSZ * LSP * 64];   // h2 fp32, layout [b][p][oc]  (134 MB)
__device__ double   g_stats1[2 * C1];
__device__ double   g_stats2[2 * C2];
__device__ uint32_t g_w2pk[3 * 4096];        // per-tap packed fp16x2 weights [tap][kp*64+oc]

// pack two floats as fp16x2: low 16 bits = `even`, high = `odd`
__device__ __forceinline__ uint32_t packh(float even, float odd) {
    uint32_t r;
    asm("cvt.rn.f16x2.f32 %0, %1, %2;" : "=r"(r) : "f"(odd), "f"(even));
    return r;
}
__device__ __forceinline__ float h16f(float v) {
    return __half2float(__float2half_rn(v));
}

// ================================================================
// prep: zero stats + pre-pack w2 into fp16x2 per-tap layout.
__global__ void k_prep(const float* __restrict__ w2) {
    int t = threadIdx.x;
    if (t < 2 * C1) g_stats1[t] = 0.0;
    if (t < 2 * C2) g_stats2[t] = 0.0;
    for (int i = t; i < 3 * 4096; i += 256) {
        int tap = i >> 12, r = i & 4095;
        int kp = r >> 6, oc = r & 63;
        float v0 = w2[(2 * kp) * 192 + oc * 3 + (2 - tap)];
        float v1 = w2[(2 * kp + 1) * 192 + oc * 3 + (2 - tap)];
        g_w2pk[i] = packh(v0, v1);
    }
}

// ------------------------------------------------------------------
// images (given = probs[:8]/max — sum-normalization cancels) + conv1 stats.
__global__ void k_imgstats(const float* __restrict__ x, const float* __restrict__ qp,
                           const float* __restrict__ w1, const float* __restrict__ b1) {
    __shared__ float sh[64][34];
    int tid = threadIdx.x;
    int b0 = blockIdx.x * 64;

    {   // phase A: one patch per thread
        int r = tid >> 2, g = tid & 3;
        int b = b0 + r;
        float c[4], s[4];
#pragma unroll
        for (int q = 0; q < 4; q++) {
            float th = 0.5f * (x[b * 4 + q] + qp[g * 4 + q]);
            c[q] = cosf(th);
            s[q] = sinf(th);
        }
        float p[8];
        float mx = 0.f;
#pragma unroll
        for (int i = 0; i < 8; i++) {
            float a = c[0];
            a *= ((i >> 2) & 1) ? s[1] : c[1];
            a *= ((i >> 1) & 1) ? s[2] : c[2];
            a *= (i & 1)        ? s[3] : c[3];
            float pp = a * a;
            p[i] = pp;
            mx = fmaxf(mx, pp);
        }
        float inv = 1.0f / mx;
#pragma unroll
        for (int i = 0; i < 8; i++) {
            float v = p[i] * inv;
            sh[r][g * 8 + i + 1] = v;
            g_images[b * 32 + g * 8 + i] = v;
        }
        if (g == 0) sh[r][0] = 0.f;
        if (g == 3) sh[r][33] = 0.f;
    }
    __syncthreads();

    {   // phase B: conv1+relu stats; thread = (oc, row-half)
        int oc = tid & 127, half = tid >> 7;
        float wA = w1[oc * 3 + 2], wB = w1[oc * 3 + 1], wC = w1[oc * 3 + 0], bb = b1[oc];
        float sum = 0.f, sq = 0.f;
        for (int rr = 0; rr < 32; rr++) {
            const float* row = sh[half * 32 + rr];
#pragma unroll
            for (int p = 0; p < 32; p++) {
                float y = bb + row[p] * wA + row[p + 1] * wB + row[p + 2] * wC;
                y = fmaxf(y, 0.f);
                sum += y;
                sq += y * y;
            }
        }
        atomicAdd(&g_stats1[oc], (double)sum);
        atomicAdd(&g_stats1[C1 + oc], (double)sq);
    }
}

// ------------------------------------------------------------------
// conv2 via mma.sync fp16 (m16n8k16), 2-term split (A exact hi/lo, B single).
#define OFF_AH 0          // 4*34*68 = 9248 words
#define OFF_AL 9248
#define OFF_B0 18496      // 4608 words
#define OFF_B1 23104      // 4608 words
#define SM_FLOATS 27712   // 110848 bytes

__global__ void __launch_bounds__(256, 2)
k_conv2(const float* __restrict__ w1, const float* __restrict__ b1,
        const float* __restrict__ g1, const float* __restrict__ be1,
        const float* __restrict__ b2) {
    extern __shared__ float sm[];
    uint32_t* sAH = (uint32_t*)(sm + OFF_AH);
    uint32_t* sAL = (uint32_t*)(sm + OFF_AL);
    uint32_t* sB0 = (uint32_t*)(sm + OFF_B0);
    uint32_t* sB1 = (uint32_t*)(sm + OFF_B1);
    float* sp   = sm + OFF_B1;         // overlay: prologue only
    float* simg = sm + OFF_B1 + 768;
    float* red  = sm + OFF_B1;         // overlay: epilogue only

    int tid = threadIdx.x;
    int wid = tid >> 5, lid = tid & 31;
    int g = lid >> 2, q = lid & 3;
    int bbase = blockIdx.x * 4;

    // --- phase 0: conv1 params + fin1 + images ---
    for (int i = tid; i < 128; i += 256) {
        sp[i * 6 + 0] = w1[i * 3 + 0];
        sp[i * 6 + 1] = w1[i * 3 + 1];
        sp[i * 6 + 2] = w1[i * 3 + 2];
        sp[i * 6 + 3] = b1[i];
        double N = 524288.0;
        double mean = g_stats1[i] / N;
        double var = g_stats1[C1 + i] / N - mean * mean;
        float a = g1[i] * (float)(1.0 / sqrt(var + 1e-5));
        sp[i * 6 + 4] = a;
        sp[i * 6 + 5] = be1[i] - (float)mean * a;
    }
    for (int i = tid; i < 4 * 32; i += 256) {
        int bl = i >> 5, p = i & 31;
        simg[bl * 34 + p + 1] = g_images[(bbase + bl) * 32 + p];
    }
    if (tid < 4) { simg[tid * 34] = 0.f; simg[tid * 34 + 33] = 0.f; }
    __syncthreads();

    // --- phase 1: h1n exact fp16 hi/lo split + stage B(tap0)->B0 ---
    for (int idx = tid; idx < 4 * 34 * 64; idx += 256) {
        int bl = idx / 2176, r = idx - bl * 2176;
        int q0 = r >> 6, u = r & 63;
        float v0 = 0.f, v1 = 0.f;
        if (q0 >= 1 && q0 <= 32) {
            int p = q0 - 1;
            float i0 = simg[bl * 34 + p], i1 = simg[bl * 34 + p + 1], i2 = simg[bl * 34 + p + 2];
            const float* p0 = &sp[(2 * u) * 6];
            float y0 = p0[3] + i0 * p0[2] + i1 * p0[1] + i2 * p0[0];
            v0 = fmaf(p0[4], fmaxf(y0, 0.f), p0[5]);
            const float* p1 = &sp[(2 * u + 1) * 6];
            float y1 = p1[3] + i0 * p1[2] + i1 * p1[1] + i2 * p1[0];
            v1 = fmaf(p1[4], fmaxf(y1, 0.f), p1[5]);
        }
        int o = (bl * 34 + q0) * 68 + u;
        sAH[o] = packh(v0, v1);
        sAL[o] = packh(v0 - h16f(v0), v1 - h16f(v1));
    }
    {   // vectorized B stage: tap0 -> B0
        const uint4* src = (const uint4*)g_w2pk;
#pragma unroll
        for (int i = tid; i < 1024; i += 256) {
            int kp = i >> 4, oc4 = (i & 15) * 4;
            *(uint4*)(sB0 + kp * 72 + oc4) = src[i];
        }
    }
    __syncthreads();

    // --- main: warp tile 32 rows (batch row bl) x 32 oc ---
    int bl = wid >> 1;
    int n0 = (wid & 1) * 32;

    float accH[2][4][4], accL[2][4][4];
#pragma unroll
    for (int mt = 0; mt < 2; mt++)
#pragma unroll
        for (int j = 0; j < 4; j++)
#pragma unroll
            for (int v = 0; v < 4; v++) { accH[mt][j][v] = 0.f; accL[mt][j][v] = 0.f; }

#define MMA_TAP(tap, SB) do { \
    _Pragma("unroll 2") \
    for (int kk = 0; kk < 8; kk++) { \
        int kb2 = kk * 8; \
        uint32_t AH[2][4], AL[2][4]; \
        _Pragma("unroll") \
        for (int mt = 0; mt < 2; mt++) { \
            int base = bl * 2312 + (mt * 16 + g + (tap)) * 68 + kb2 + q; \
            AH[mt][0] = sAH[base];       AL[mt][0] = sAL[base]; \
            AH[mt][1] = sAH[base + 544]; AL[mt][1] = sAL[base + 544]; \
            AH[mt][2] = sAH[base + 4];   AL[mt][2] = sAL[base + 4]; \
            AH[mt][3] = sAH[base + 548]; AL[mt][3] = sAL[base + 548]; \
        } \
        uint32_t B[4][2]; \
        _Pragma("unroll") \
        for (int j = 0; j < 4; j++) { \
            int n = n0 + 8 * j + g; \
            B[j][0] = (SB)[(kb2 + q) * 72 + n]; \
            B[j][1] = (SB)[(kb2 + q + 4) * 72 + n]; \
        } \
        _Pragma("unroll") \
        for (int mt = 0; mt < 2; mt++) \
            _Pragma("unroll") \
            for (int j = 0; j < 4; j++) \
                asm volatile( \
                    "mma.sync.aligned.m16n8k16.row.col.f32.f16.f16.f32 " \
                    "{%0,%1,%2,%3},{%4,%5,%6,%7},{%8,%9},{%0,%1,%2,%3};" \
                    : "+f"(accH[mt][j][0]), "+f"(accH[mt][j][1]), \
                      "+f"(accH[mt][j][2]), "+f"(accH[mt][j][3]) \
                    : "r"(AH[mt][0]), "r"(AH[mt][1]), "r"(AH[mt][2]), "r"(AH[mt][3]), \
                      "r"(B[j][0]), "r"(B[j][1])); \
        _Pragma("unroll") \
        for (int mt = 0; mt < 2; mt++) \
            _Pragma("unroll") \
            for (int j = 0; j < 4; j++) \
                asm volatile( \
                    "mma.sync.aligned.m16n8k16.row.col.f32.f16.f16.f32 " \
                    "{%0,%1,%2,%3},{%4,%5,%6,%7},{%8,%9},{%0,%1,%2,%3};" \
                    : "+f"(accL[mt][j][0]), "+f"(accL[mt][j][1]), \
                      "+f"(accL[mt][j][2]), "+f"(accL[mt][j][3]) \
                    : "r"(AL[mt][0]), "r"(AL[mt][1]), "r"(AL[mt][2]), "r"(AL[mt][3]), \
                      "r"(B[j][0]), "r"(B[j][1])); \
    } } while (0)

#define STAGE_B(tap, SB) do { \
    const uint4* src = (const uint4*)(g_w2pk + (tap) * 4096); \
    _Pragma("unroll") \
    for (int i = tid; i < 1024; i += 256) { \
        int kp = i >> 4, oc4 = (i & 15) * 4; \
        *(uint4*)((SB) + kp * 72 + oc4) = src[i]; \
    } } while (0)

    STAGE_B(1, sB1);
    MMA_TAP(0, sB0);
    __syncthreads();
    STAGE_B(2, sB0);
    MMA_TAP(1, sB1);
    __syncthreads();
    MMA_TAP(2, sB0);

    // --- epilogue: merge, bias+relu, store fp32 h2 [b][p][oc] via float2, stats ---
    __syncthreads();
    if (tid < 128) red[tid] = 0.f;
    __syncthreads();

    int b = bbase + bl;
    float bias[4][2];
#pragma unroll
    for (int j = 0; j < 4; j++) {
        bias[j][0] = __ldg(&b2[n0 + 8 * j + 2 * q]);
        bias[j][1] = __ldg(&b2[n0 + 8 * j + 2 * q + 1]);
    }
    float ssum[4][2], ssq[4][2];
#pragma unroll
    for (int j = 0; j < 4; j++)
        for (int c = 0; c < 2; c++) { ssum[j][c] = 0.f; ssq[j][c] = 0.f; }

    float2* h2v = (float2*)g_h2f;
#pragma unroll
    for (int mt = 0; mt < 2; mt++)
#pragma unroll
        for (int j = 0; j < 4; j++)
#pragma unroll
            for (int h = 0; h < 2; h++) {
                int p = mt * 16 + h * 8 + g;
                float y0 = fmaxf(accH[mt][j][h * 2 + 0] + accL[mt][j][h * 2 + 0] + bias[j][0], 0.f);
                float y1 = fmaxf(accH[mt][j][h * 2 + 1] + accL[mt][j][h * 2 + 1] + bias[j][1], 0.f);
                h2v[(b * 32 + p) * 32 + (n0 + 8 * j) / 2 + q] = make_float2(y0, y1);
                ssum[j][0] += y0; ssq[j][0] += y0 * y0;
                ssum[j][1] += y1; ssq[j][1] += y1 * y1;
            }
#pragma unroll
    for (int j = 0; j < 4; j++)
#pragma unroll
        for (int c = 0; c < 2; c++) {
#pragma unroll
            for (int mk = 4; mk <= 16; mk <<= 1) {
                ssum[j][c] += __shfl_xor_sync(0xffffffffu, ssum[j][c], mk);
                ssq[j][c]  += __shfl_xor_sync(0xffffffffu, ssq[j][c], mk);
            }
        }
    if (lid < 4) {
#pragma unroll
        for (int j = 0; j < 4; j++)
#pragma unroll
            for (int c = 0; c < 2; c++) {
                int oc = n0 + 8 * j + 2 * lid + c;
                atomicAdd(&red[oc], ssum[j][c]);
                atomicAdd(&red[64 + oc], ssq[j][c]);
            }
    }
    __syncthreads();
    if (tid < 128) atomicAdd(&g_stats2[tid], (double)red[tid]);
}

// ------------------------------------------------------------------
// conv3: fin2 folded, BN folded (w3a + gated S), h2 staged in dynamic smem.
// 256 threads = 2 threads per output (even/odd lanes split 64 channels,
// combined with shfl_xor(.,1)); 4 batch rows per block.
// Dynamic smem word offsets:
#define C3_SH2   0                    // 4*34*76 = 10336
#define C3_W3A   10336                // 192
#define C3_SAC   10528                // 128
#define C3_SS    10656                // 3
#define C3_WORDS 10660                // 42640 bytes

__global__ void __launch_bounds__(256)
k_conv3(const float* __restrict__ g2, const float* __restrict__ be2,
        const float* __restrict__ w3, const float* __restrict__ b3,
        float* __restrict__ out) {
    extern __shared__ float sc3[];
    float* sh2  = sc3 + C3_SH2;
    float* sw3a = sc3 + C3_W3A;
    float* sac  = sc3 + C3_SAC;
    float* sS   = sc3 + C3_SS;

    int tid = threadIdx.x;
    if (tid < 64) {
        double N = 524288.0;
        double mean = g_stats2[tid] / N;
        double var = g_stats2[C2 + tid] / N - mean * mean;
        float a = g2[tid] * (float)(1.0 / sqrt(var + 1e-5));
        sac[tid] = a;
        sac[64 + tid] = be2[tid] - (float)mean * a;
    }
    // zero halo rows: 4 b x 2 rows x 76 words
    for (int i = tid; i < 608; i += 256) {
        int b = i / 152, r = (i / 76) & 1, w = i % 76;
        sh2[(b * 34 + (r ? 33 : 0)) * 76 + w] = 0.f;
    }
    __syncthreads();
    if (tid < 64) {
        float a = sac[tid];
        sw3a[tid * 3 + 0] = w3[tid * 3 + 0] * a;
        sw3a[tid * 3 + 1] = w3[tid * 3 + 1] * a;
        sw3a[tid * 3 + 2] = w3[tid * 3 + 2] * a;
    }
    if (tid < 3) {
        float s = 0.f;
        for (int ic = 0; ic < 64; ic++) s += w3[ic * 3 + tid] * sac[64 + ic];
        sS[tid] = s;
    }
    // stage 4 rows of h2: 2048 uint4, fully coalesced
    {
        const uint4* src = (const uint4*)g_h2f + (size_t)blockIdx.x * 2048;
        for (int i = tid; i < 2048; i += 256) {
            int b = i >> 9, r = (i >> 4) & 31, c = i & 15;
            *(uint4*)(sh2 + (b * 34 + r + 1) * 76 + c * 4) = src[i];
        }
    }
    __syncthreads();

    int half = tid & 1;          // channel half; partner lane = lane^1 (same warp)
    int u = tid >> 1;            // 0..127
    int b = u >> 5, p = u & 31;
    const float* base = sh2 + b * 34 * 76 + half * 32;
    const float* r0 = base + p * 76;            // h2[p-1] (halo at p=0)
    const float* r1 = base + (p + 1) * 76;      // h2[p]
    const float* r2 = base + (p + 2) * 76;      // h2[p+1] (halo at p=31)

    float acc = half ? 0.f
                     : (b3[0] + sS[1] + (p > 0 ? sS[2] : 0.f) + (p < 31 ? sS[0] : 0.f));
#pragma unroll
    for (int i = 0; i < 8; i++) {
        float4 xm = *(const float4*)(r0 + i * 4);
        float4 x0 = *(const float4*)(r1 + i * 4);
        float4 xp = *(const float4*)(r2 + i * 4);
        const float* w0 = &sw3a[(half * 8 + i) * 12];
        acc += xm.x * w0[2]  + x0.x * w0[1]  + xp.x * w0[0];
        acc += xm.y * w0[5]  + x0.y * w0[4]  + xp.y * w0[3];
        acc += xm.z * w0[8]  + x0.z * w0[7]  + xp.z * w0[6];
        acc += xm.w * w0[11] + x0.w * w0[10] + xp.w * w0[9];
    }
    acc += __shfl_xor_sync(0xffffffffu, acc, 1);
    if (half == 0)
        out[(size_t)(blockIdx.x * 4 + b) * 32 + p] = tanhf(acc);
}

// ------------------------------------------------------------------
extern "C" void kernel_launch(void* const* d_in, const int* in_sizes, int n_in,
                              void* d_out, int out_size) {
    const float* x   = (const float*)d_in[0];
    const float* qp  = (const float*)d_in[1];
    const float* w1  = (const float*)d_in[2];
    const float* b1  = (const float*)d_in[3];
    const float* g1  = (const float*)d_in[4];
    const float* be1 = (const float*)d_in[5];
    const float* w2  = (const float*)d_in[6];
    const float* b2  = (const float*)d_in[7];
    const float* g2  = (const float*)d_in[8];
    const float* be2 = (const float*)d_in[9];
    const float* w3  = (const float*)d_in[10];
    const float* b3  = (const float*)d_in[11];
    float* out = (float*)d_out;

    const int smem_bytes = SM_FLOATS * (int)sizeof(float);   // 110848 B
    cudaFuncSetAttribute(k_conv2, cudaFuncAttributeMaxDynamicSharedMemorySize, smem_bytes);
    const int c3_bytes = C3_WORDS * (int)sizeof(float);      // 42640 B
    cudaFuncSetAttribute(k_conv3, cudaFuncAttributeMaxDynamicSharedMemorySize, c3_bytes);

    k_prep<<<1, 256>>>(w2);
    k_imgstats<<<BSZ / 64, 256>>>(x, qp, w1, b1);
    k_conv2<<<BSZ / 4, 256, smem_bytes>>>(w1, b1, g1, be1, b2);
    k_conv3<<<BSZ / 4, 256, c3_bytes>>>(g2, be2, w3, b3, out);
}

// round 16
// speedup vs baseline: 3.4531x; 1.1379x over previous
#include <cuda_runtime.h>
#include <cuda_fp16.h>
#include <math.h>
#include <stdint.h>

#define BSZ   16384
#define LSP   32
#define C1    128
#define C2    64

// ---- persistent device scratch ----
__device__ float    g_images[BSZ * LSP];
__device__ float    g_h2f[BSZ * LSP * 64];   // h2 fp32, layout [b][p][oc]  (134 MB)
__device__ double   g_stats1[2 * C1];
__device__ double   g_stats2[2 * C2];
__device__ uint32_t g_w2pk[3 * 4096];        // per-tap packed fp16x2 weights [tap][kp*64+oc]

// pack two floats as fp16x2: low 16 bits = `even`, high = `odd`
__device__ __forceinline__ uint32_t packh(float even, float odd) {
    uint32_t r;
    asm("cvt.rn.f16x2.f32 %0, %1, %2;" : "=r"(r) : "f"(odd), "f"(even));
    return r;
}
__device__ __forceinline__ float h16f(float v) {
    return __half2float(__float2half_rn(v));
}

// ================================================================
// prep: zero stats + pre-pack w2 into fp16x2 per-tap layout.
__global__ void k_prep(const float* __restrict__ w2) {
    int t = threadIdx.x;
    if (t < 2 * C1) g_stats1[t] = 0.0;
    if (t < 2 * C2) g_stats2[t] = 0.0;
    for (int i = t; i < 3 * 4096; i += 256) {
        int tap = i >> 12, r = i & 4095;
        int kp = r >> 6, oc = r & 63;
        float v0 = w2[(2 * kp) * 192 + oc * 3 + (2 - tap)];
        float v1 = w2[(2 * kp + 1) * 192 + oc * 3 + (2 - tap)];
        g_w2pk[i] = packh(v0, v1);
    }
}

// ------------------------------------------------------------------
// images (given = probs[:8]/max — sum-normalization cancels) + conv1 stats.
__global__ void k_imgstats(const float* __restrict__ x, const float* __restrict__ qp,
                           const float* __restrict__ w1, const float* __restrict__ b1) {
    __shared__ float sh[64][34];
    int tid = threadIdx.x;
    int b0 = blockIdx.x * 64;

    {   // phase A: one patch per thread
        int r = tid >> 2, g = tid & 3;
        int b = b0 + r;
        float c[4], s[4];
#pragma unroll
        for (int q = 0; q < 4; q++) {
            float th = 0.5f * (x[b * 4 + q] + qp[g * 4 + q]);
            c[q] = cosf(th);
            s[q] = sinf(th);
        }
        float p[8];
        float mx = 0.f;
#pragma unroll
        for (int i = 0; i < 8; i++) {
            float a = c[0];
            a *= ((i >> 2) & 1) ? s[1] : c[1];
            a *= ((i >> 1) & 1) ? s[2] : c[2];
            a *= (i & 1)        ? s[3] : c[3];
            float pp = a * a;
            p[i] = pp;
            mx = fmaxf(mx, pp);
        }
        float inv = 1.0f / mx;
#pragma unroll
        for (int i = 0; i < 8; i++) {
            float v = p[i] * inv;
            sh[r][g * 8 + i + 1] = v;
            g_images[b * 32 + g * 8 + i] = v;
        }
        if (g == 0) sh[r][0] = 0.f;
        if (g == 3) sh[r][33] = 0.f;
    }
    __syncthreads();

    {   // phase B: conv1+relu stats; thread = (oc, row-half)
        int oc = tid & 127, half = tid >> 7;
        float wA = w1[oc * 3 + 2], wB = w1[oc * 3 + 1], wC = w1[oc * 3 + 0], bb = b1[oc];
        float sum = 0.f, sq = 0.f;
        for (int rr = 0; rr < 32; rr++) {
            const float* row = sh[half * 32 + rr];
#pragma unroll
            for (int p = 0; p < 32; p++) {
                float y = bb + row[p] * wA + row[p + 1] * wB + row[p + 2] * wC;
                y = fmaxf(y, 0.f);
                sum += y;
                sq += y * y;
            }
        }
        atomicAdd(&g_stats1[oc], (double)sum);
        atomicAdd(&g_stats1[C1 + oc], (double)sq);
    }
}

// ------------------------------------------------------------------
// conv2 via mma.sync fp16 (m16n8k16), 2-term split (A exact hi/lo, B single).
#define OFF_AH 0          // 4*34*68 = 9248 words
#define OFF_AL 9248
#define OFF_B0 18496      // 4608 words
#define OFF_B1 23104      // 4608 words
#define SM_FLOATS 27712   // 110848 bytes

__global__ void __launch_bounds__(256, 2)
k_conv2(const float* __restrict__ w1, const float* __restrict__ b1,
        const float* __restrict__ g1, const float* __restrict__ be1,
        const float* __restrict__ b2) {
    extern __shared__ float sm[];
    uint32_t* sAH = (uint32_t*)(sm + OFF_AH);
    uint32_t* sAL = (uint32_t*)(sm + OFF_AL);
    uint32_t* sB0 = (uint32_t*)(sm + OFF_B0);
    uint32_t* sB1 = (uint32_t*)(sm + OFF_B1);
    float* sp   = sm + OFF_B1;         // overlay: prologue only
    float* simg = sm + OFF_B1 + 768;
    float* red  = sm + OFF_B1;         // overlay: epilogue only

    int tid = threadIdx.x;
    int wid = tid >> 5, lid = tid & 31;
    int g = lid >> 2, q = lid & 3;
    int bbase = blockIdx.x * 4;

    // --- phase 0: conv1 params + fin1 + images ---
    for (int i = tid; i < 128; i += 256) {
        sp[i * 6 + 0] = w1[i * 3 + 0];
        sp[i * 6 + 1] = w1[i * 3 + 1];
        sp[i * 6 + 2] = w1[i * 3 + 2];
        sp[i * 6 + 3] = b1[i];
        double N = 524288.0;
        double mean = g_stats1[i] / N;
        double var = g_stats1[C1 + i] / N - mean * mean;
        float a = g1[i] * (float)(1.0 / sqrt(var + 1e-5));
        sp[i * 6 + 4] = a;
        sp[i * 6 + 5] = be1[i] - (float)mean * a;
    }
    for (int i = tid; i < 4 * 32; i += 256) {
        int bl = i >> 5, p = i & 31;
        simg[bl * 34 + p + 1] = g_images[(bbase + bl) * 32 + p];
    }
    if (tid < 4) { simg[tid * 34] = 0.f; simg[tid * 34 + 33] = 0.f; }
    __syncthreads();

    // --- phase 1: h1n exact fp16 hi/lo split + stage B(tap0)->B0 ---
    for (int idx = tid; idx < 4 * 34 * 64; idx += 256) {
        int bl = idx / 2176, r = idx - bl * 2176;
        int q0 = r >> 6, u = r & 63;
        float v0 = 0.f, v1 = 0.f;
        if (q0 >= 1 && q0 <= 32) {
            int p = q0 - 1;
            float i0 = simg[bl * 34 + p], i1 = simg[bl * 34 + p + 1], i2 = simg[bl * 34 + p + 2];
            const float* p0 = &sp[(2 * u) * 6];
            float y0 = p0[3] + i0 * p0[2] + i1 * p0[1] + i2 * p0[0];
            v0 = fmaf(p0[4], fmaxf(y0, 0.f), p0[5]);
            const float* p1 = &sp[(2 * u + 1) * 6];
            float y1 = p1[3] + i0 * p1[2] + i1 * p1[1] + i2 * p1[0];
            v1 = fmaf(p1[4], fmaxf(y1, 0.f), p1[5]);
        }
        int o = (bl * 34 + q0) * 68 + u;
        sAH[o] = packh(v0, v1);
        sAL[o] = packh(v0 - h16f(v0), v1 - h16f(v1));
    }
    {   // vectorized B stage: tap0 -> B0
        const uint4* src = (const uint4*)g_w2pk;
#pragma unroll
        for (int i = tid; i < 1024; i += 256) {
            int kp = i >> 4, oc4 = (i & 15) * 4;
            *(uint4*)(sB0 + kp * 72 + oc4) = src[i];
        }
    }
    __syncthreads();

    // --- main: warp tile 32 rows (batch row bl) x 32 oc ---
    int bl = wid >> 1;
    int n0 = (wid & 1) * 32;

    float accH[2][4][4], accL[2][4][4];
#pragma unroll
    for (int mt = 0; mt < 2; mt++)
#pragma unroll
        for (int j = 0; j < 4; j++)
#pragma unroll
            for (int v = 0; v < 4; v++) { accH[mt][j][v] = 0.f; accL[mt][j][v] = 0.f; }

#define MMA_TAP(tap, SB) do { \
    _Pragma("unroll 2") \
    for (int kk = 0; kk < 8; kk++) { \
        int kb2 = kk * 8; \
        uint32_t AH[2][4], AL[2][4]; \
        _Pragma("unroll") \
        for (int mt = 0; mt < 2; mt++) { \
            int base = bl * 2312 + (mt * 16 + g + (tap)) * 68 + kb2 + q; \
            AH[mt][0] = sAH[base];       AL[mt][0] = sAL[base]; \
            AH[mt][1] = sAH[base + 544]; AL[mt][1] = sAL[base + 544]; \
            AH[mt][2] = sAH[base + 4];   AL[mt][2] = sAL[base + 4]; \
            AH[mt][3] = sAH[base + 548]; AL[mt][3] = sAL[base + 548]; \
        } \
        uint32_t B[4][2]; \
        _Pragma("unroll") \
        for (int j = 0; j < 4; j++) { \
            int n = n0 + 8 * j + g; \
            B[j][0] = (SB)[(kb2 + q) * 72 + n]; \
            B[j][1] = (SB)[(kb2 + q + 4) * 72 + n]; \
        } \
        _Pragma("unroll") \
        for (int mt = 0; mt < 2; mt++) \
            _Pragma("unroll") \
            for (int j = 0; j < 4; j++) \
                asm volatile( \
                    "mma.sync.aligned.m16n8k16.row.col.f32.f16.f16.f32 " \
                    "{%0,%1,%2,%3},{%4,%5,%6,%7},{%8,%9},{%0,%1,%2,%3};" \
                    : "+f"(accH[mt][j][0]), "+f"(accH[mt][j][1]), \
                      "+f"(accH[mt][j][2]), "+f"(accH[mt][j][3]) \
                    : "r"(AH[mt][0]), "r"(AH[mt][1]), "r"(AH[mt][2]), "r"(AH[mt][3]), \
                      "r"(B[j][0]), "r"(B[j][1])); \
        _Pragma("unroll") \
        for (int mt = 0; mt < 2; mt++) \
            _Pragma("unroll") \
            for (int j = 0; j < 4; j++) \
                asm volatile( \
                    "mma.sync.aligned.m16n8k16.row.col.f32.f16.f16.f32 " \
                    "{%0,%1,%2,%3},{%4,%5,%6,%7},{%8,%9},{%0,%1,%2,%3};" \
                    : "+f"(accL[mt][j][0]), "+f"(accL[mt][j][1]), \
                      "+f"(accL[mt][j][2]), "+f"(accL[mt][j][3]) \
                    : "r"(AL[mt][0]), "r"(AL[mt][1]), "r"(AL[mt][2]), "r"(AL[mt][3]), \
                      "r"(B[j][0]), "r"(B[j][1])); \
    } } while (0)

#define STAGE_B(tap, SB) do { \
    const uint4* src = (const uint4*)(g_w2pk + (tap) * 4096); \
    _Pragma("unroll") \
    for (int i = tid; i < 1024; i += 256) { \
        int kp = i >> 4, oc4 = (i & 15) * 4; \
        *(uint4*)((SB) + kp * 72 + oc4) = src[i]; \
    } } while (0)

    STAGE_B(1, sB1);
    MMA_TAP(0, sB0);
    __syncthreads();
    STAGE_B(2, sB0);
    MMA_TAP(1, sB1);
    __syncthreads();
    MMA_TAP(2, sB0);

    // --- epilogue: merge, bias+relu, store fp32 h2 [b][p][oc] via float2, stats ---
    __syncthreads();
    if (tid < 128) red[tid] = 0.f;
    __syncthreads();

    int b = bbase + bl;
    float bias[4][2];
#pragma unroll
    for (int j = 0; j < 4; j++) {
        bias[j][0] = __ldg(&b2[n0 + 8 * j + 2 * q]);
        bias[j][1] = __ldg(&b2[n0 + 8 * j + 2 * q + 1]);
    }
    float ssum[4][2], ssq[4][2];
#pragma unroll
    for (int j = 0; j < 4; j++)
        for (int c = 0; c < 2; c++) { ssum[j][c] = 0.f; ssq[j][c] = 0.f; }

    float2* h2v = (float2*)g_h2f;
#pragma unroll
    for (int mt = 0; mt < 2; mt++)
#pragma unroll
        for (int j = 0; j < 4; j++)
#pragma unroll
            for (int h = 0; h < 2; h++) {
                int p = mt * 16 + h * 8 + g;
                float y0 = fmaxf(accH[mt][j][h * 2 + 0] + accL[mt][j][h * 2 + 0] + bias[j][0], 0.f);
                float y1 = fmaxf(accH[mt][j][h * 2 + 1] + accL[mt][j][h * 2 + 1] + bias[j][1], 0.f);
                h2v[(b * 32 + p) * 32 + (n0 + 8 * j) / 2 + q] = make_float2(y0, y1);
                ssum[j][0] += y0; ssq[j][0] += y0 * y0;
                ssum[j][1] += y1; ssq[j][1] += y1 * y1;
            }
#pragma unroll
    for (int j = 0; j < 4; j++)
#pragma unroll
        for (int c = 0; c < 2; c++) {
#pragma unroll
            for (int mk = 4; mk <= 16; mk <<= 1) {
                ssum[j][c] += __shfl_xor_sync(0xffffffffu, ssum[j][c], mk);
                ssq[j][c]  += __shfl_xor_sync(0xffffffffu, ssq[j][c], mk);
            }
        }
    if (lid < 4) {
#pragma unroll
        for (int j = 0; j < 4; j++)
#pragma unroll
            for (int c = 0; c < 2; c++) {
                int oc = n0 + 8 * j + 2 * lid + c;
                atomicAdd(&red[oc], ssum[j][c]);
                atomicAdd(&red[64 + oc], ssq[j][c]);
            }
    }
    __syncthreads();
    if (tid < 128) atomicAdd(&g_stats2[tid], (double)red[tid]);
}

// ------------------------------------------------------------------
// conv3: sliding-scatter, NO smem staging. Thread = (b-local 0..15, oc-quad 0..15).
// Streams 32 rows of h2 [b][p][oc] (1 LDG.128 each, loaded exactly once),
// scatters into 32 register accumulators; butterfly-reduce over 16 quads
// (lanes of same b-group); each lane emits 2 outputs with gated S constants.
__global__ void __launch_bounds__(256)
k_conv3(const float* __restrict__ g2, const float* __restrict__ be2,
        const float* __restrict__ w3, const float* __restrict__ b3,
        float* __restrict__ out) {
    __shared__ float sw3a[192];
    __shared__ float sac[128];
    __shared__ float sS[3];

    int tid = threadIdx.x;
    if (tid < 64) {
        double N = 524288.0;
        double mean = g_stats2[tid] / N;
        double var = g_stats2[C2 + tid] / N - mean * mean;
        float a = g2[tid] * (float)(1.0 / sqrt(var + 1e-5));
        sac[tid] = a;
        sac[64 + tid] = be2[tid] - (float)mean * a;
    }
    __syncthreads();
    if (tid < 64) {
        float a = sac[tid];
        sw3a[tid * 3 + 0] = w3[tid * 3 + 0] * a;
        sw3a[tid * 3 + 1] = w3[tid * 3 + 1] * a;
        sw3a[tid * 3 + 2] = w3[tid * 3 + 2] * a;
    }
    if (tid < 3) {
        float s = 0.f;
        for (int ic = 0; ic < 64; ic++) s += w3[ic * 3 + tid] * sac[64 + ic];
        sS[tid] = s;
    }
    __syncthreads();

    int bl = tid >> 4;           // local batch row 0..15
    int quad = tid & 15;         // oc quad (4 channels)
    size_t bglob = (size_t)blockIdx.x * 16 + bl;
    const float4* src = (const float4*)(g_h2f + bglob * 32 * 64) + quad;

    // weights for my 4 channels x 3 taps
    float w[3][4];
#pragma unroll
    for (int c = 0; c < 4; c++) {
        int ic = quad * 4 + c;
        w[0][c] = sw3a[ic * 3 + 0];   // h2 row r -> out r-1
        w[1][c] = sw3a[ic * 3 + 1];   // -> out r
        w[2][c] = sw3a[ic * 3 + 2];   // -> out r+1
    }

    float acc[32];
#pragma unroll
    for (int p = 0; p < 32; p++) acc[p] = 0.f;

#pragma unroll
    for (int r = 0; r < 32; r++) {
        float4 v = src[r * 16];
        float dm = v.x * w[0][0] + v.y * w[0][1] + v.z * w[0][2] + v.w * w[0][3];
        float d0 = v.x * w[1][0] + v.y * w[1][1] + v.z * w[1][2] + v.w * w[1][3];
        float dp = v.x * w[2][0] + v.y * w[2][1] + v.z * w[2][2] + v.w * w[2][3];
        if (r > 0)  acc[r - 1] += dm;
        acc[r] += d0;
        if (r < 31) acc[r + 1] += dp;
    }

    // butterfly over quad bits (lanes of same b-group: lane = (bl&1)*16 + quad)
#pragma unroll
    for (int mk = 1; mk <= 8; mk <<= 1)
#pragma unroll
        for (int p = 0; p < 32; p++)
            acc[p] += __shfl_xor_sync(0xffffffffu, acc[p], mk);

    float base = __ldg(&b3[0]) + sS[1];
#pragma unroll
    for (int e = 0; e < 2; e++) {
        int p = quad * 2 + e;
        float a = acc[p] + base + (p > 0 ? sS[2] : 0.f) + (p < 31 ? sS[0] : 0.f);
        out[bglob * 32 + p] = tanhf(a);
    }
}

// ------------------------------------------------------------------
extern "C" void kernel_launch(void* const* d_in, const int* in_sizes, int n_in,
                              void* d_out, int out_size) {
    const float* x   = (const float*)d_in[0];
    const float* qp  = (const float*)d_in[1];
    const float* w1  = (const float*)d_in[2];
    const float* b1  = (const float*)d_in[3];
    const float* g1  = (const float*)d_in[4];
    const float* be1 = (const float*)d_in[5];
    const float* w2  = (const float*)d_in[6];
    const float* b2  = (const float*)d_in[7];
    const float* g2  = (const float*)d_in[8];
    const float* be2 = (const float*)d_in[9];
    const float* w3  = (const float*)d_in[10];
    const float* b3  = (const float*)d_in[11];
    float* out = (float*)d_out;

    const int smem_bytes = SM_FLOATS * (int)sizeof(float);   // 110848 B
    cudaFuncSetAttribute(k_conv2, cudaFuncAttributeMaxDynamicSharedMemorySize, smem_bytes);

    k_prep<<<1, 256>>>(w2);
    k_imgstats<<<BSZ / 64, 256>>>(x, qp, w1, b1);
    k_conv2<<<BSZ / 4, 256, smem_bytes>>>(w1, b1, g1, be1, b2);
    k_conv3<<<BSZ / 16, 256>>>(g2, be2, w3, b3, out);
}

// round 17
// speedup vs baseline: 3.5049x; 1.0150x over previous
#include <cuda_runtime.h>
#include <cuda_fp16.h>
#include <math.h>
#include <stdint.h>

#define BSZ   16384
#define LSP   32
#define C1    128
#define C2    64

// ---- persistent device scratch ----
__device__ float    g_images[BSZ * LSP];
__device__ float    g_h2f[BSZ * LSP * 64];   // h2 fp32, layout [b][p][oc]  (134 MB)
__device__ double   g_stats1[2 * C1];
__device__ double   g_stats2[2 * C2];
__device__ uint32_t g_w2pk[3 * 4096];        // per-tap packed fp16x2 weights [tap][kp*64+oc]

// pack two floats as fp16x2: low 16 bits = `even`, high = `odd`
__device__ __forceinline__ uint32_t packh(float even, float odd) {
    uint32_t r;
    asm("cvt.rn.f16x2.f32 %0, %1, %2;" : "=r"(r) : "f"(odd), "f"(even));
    return r;
}
__device__ __forceinline__ float h16f(float v) {
    return __half2float(__float2half_rn(v));
}

// ================================================================
// prep: zero stats + pre-pack w2 into fp16x2 per-tap layout.
__global__ void k_prep(const float* __restrict__ w2) {
    int t = threadIdx.x;
    if (t < 2 * C1) g_stats1[t] = 0.0;
    if (t < 2 * C2) g_stats2[t] = 0.0;
    for (int i = t; i < 3 * 4096; i += 256) {
        int tap = i >> 12, r = i & 4095;
        int kp = r >> 6, oc = r & 63;
        float v0 = w2[(2 * kp) * 192 + oc * 3 + (2 - tap)];
        float v1 = w2[(2 * kp + 1) * 192 + oc * 3 + (2 - tap)];
        g_w2pk[i] = packh(v0, v1);
    }
}

// ------------------------------------------------------------------
// images (given = probs[:8]/max — sum-normalization cancels) + conv1 stats.
// 32 batch rows per block, grid 512; half-sums merged in smem so the
// double-atomic count per oc stays at 512/address.
__global__ void k_imgstats(const float* __restrict__ x, const float* __restrict__ qp,
                           const float* __restrict__ w1, const float* __restrict__ b1) {
    __shared__ float sh[32][34];
    __shared__ float sred[256];      // [oc] sum (half1), then reused
    __shared__ float sredq[256];
    int tid = threadIdx.x;
    int b0 = blockIdx.x * 32;

    {   // phase A: 128 patches, threads 0..127
        if (tid < 128) {
            int r = tid >> 2, g = tid & 3;
            int b = b0 + r;
            float c[4], s[4];
#pragma unroll
            for (int q = 0; q < 4; q++) {
                float th = 0.5f * (x[b * 4 + q] + qp[g * 4 + q]);
                c[q] = cosf(th);
                s[q] = sinf(th);
            }
            float p[8];
            float mx = 0.f;
#pragma unroll
            for (int i = 0; i < 8; i++) {
                float a = c[0];
                a *= ((i >> 2) & 1) ? s[1] : c[1];
                a *= ((i >> 1) & 1) ? s[2] : c[2];
                a *= (i & 1)        ? s[3] : c[3];
                float pp = a * a;
                p[i] = pp;
                mx = fmaxf(mx, pp);
            }
            float inv = 1.0f / mx;
#pragma unroll
            for (int i = 0; i < 8; i++) {
                float v = p[i] * inv;
                sh[r][g * 8 + i + 1] = v;
                g_images[b * 32 + g * 8 + i] = v;
            }
            if (g == 0) sh[r][0] = 0.f;
            if (g == 3) sh[r][33] = 0.f;
        }
    }
    __syncthreads();

    {   // phase B: conv1+relu stats; thread = (oc, row-half), 16 rows each
        int oc = tid & 127, half = tid >> 7;
        float wA = w1[oc * 3 + 2], wB = w1[oc * 3 + 1], wC = w1[oc * 3 + 0], bb = b1[oc];
        float sum = 0.f, sq = 0.f;
        for (int rr = 0; rr < 16; rr++) {
            const float* row = sh[half * 16 + rr];
#pragma unroll
            for (int p = 0; p < 32; p++) {
                float y = bb + row[p] * wA + row[p + 1] * wB + row[p + 2] * wC;
                y = fmaxf(y, 0.f);
                sum += y;
                sq += y * y;
            }
        }
        if (half == 1) { sred[oc] = sum; sredq[oc] = sq; }
        __syncthreads();
        if (half == 0) {
            atomicAdd(&g_stats1[oc], (double)(sum + sred[oc]));
            atomicAdd(&g_stats1[C1 + oc], (double)(sq + sredq[oc]));
        }
    }
}

// ------------------------------------------------------------------
// conv2 via mma.sync fp16 (m16n8k16), 2-term split (A exact hi/lo, B single).
#define OFF_AH 0          // 4*34*68 = 9248 words
#define OFF_AL 9248
#define OFF_B0 18496      // 4608 words
#define OFF_B1 23104      // 4608 words
#define SM_FLOATS 27712   // 110848 bytes

__global__ void __launch_bounds__(256, 2)
k_conv2(const float* __restrict__ w1, const float* __restrict__ b1,
        const float* __restrict__ g1, const float* __restrict__ be1,
        const float* __restrict__ b2) {
    extern __shared__ float sm[];
    uint32_t* sAH = (uint32_t*)(sm + OFF_AH);
    uint32_t* sAL = (uint32_t*)(sm + OFF_AL);
    uint32_t* sB0 = (uint32_t*)(sm + OFF_B0);
    uint32_t* sB1 = (uint32_t*)(sm + OFF_B1);
    float* sp   = sm + OFF_B1;         // overlay: prologue only
    float* simg = sm + OFF_B1 + 768;
    float* red  = sm + OFF_B1;         // overlay: epilogue only

    int tid = threadIdx.x;
    int wid = tid >> 5, lid = tid & 31;
    int g = lid >> 2, q = lid & 3;
    int bbase = blockIdx.x * 4;

    // --- phase 0: conv1 params + fin1 + images ---
    for (int i = tid; i < 128; i += 256) {
        sp[i * 6 + 0] = w1[i * 3 + 0];
        sp[i * 6 + 1] = w1[i * 3 + 1];
        sp[i * 6 + 2] = w1[i * 3 + 2];
        sp[i * 6 + 3] = b1[i];
        double N = 524288.0;
        double mean = g_stats1[i] / N;
        double var = g_stats1[C1 + i] / N - mean * mean;
        float a = g1[i] * (float)(1.0 / sqrt(var + 1e-5));
        sp[i * 6 + 4] = a;
        sp[i * 6 + 5] = be1[i] - (float)mean * a;
    }
    for (int i = tid; i < 4 * 32; i += 256) {
        int bl = i >> 5, p = i & 31;
        simg[bl * 34 + p + 1] = g_images[(bbase + bl) * 32 + p];
    }
    if (tid < 4) { simg[tid * 34] = 0.f; simg[tid * 34 + 33] = 0.f; }
    __syncthreads();

    // --- phase 1: h1n exact fp16 hi/lo split + stage B(tap0)->B0 ---
    for (int idx = tid; idx < 4 * 34 * 64; idx += 256) {
        int bl = idx / 2176, r = idx - bl * 2176;
        int q0 = r >> 6, u = r & 63;
        float v0 = 0.f, v1 = 0.f;
        if (q0 >= 1 && q0 <= 32) {
            int p = q0 - 1;
            float i0 = simg[bl * 34 + p], i1 = simg[bl * 34 + p + 1], i2 = simg[bl * 34 + p + 2];
            const float* p0 = &sp[(2 * u) * 6];
            float y0 = p0[3] + i0 * p0[2] + i1 * p0[1] + i2 * p0[0];
            v0 = fmaf(p0[4], fmaxf(y0, 0.f), p0[5]);
            const float* p1 = &sp[(2 * u + 1) * 6];
            float y1 = p1[3] + i0 * p1[2] + i1 * p1[1] + i2 * p1[0];
            v1 = fmaf(p1[4], fmaxf(y1, 0.f), p1[5]);
        }
        int o = (bl * 34 + q0) * 68 + u;
        sAH[o] = packh(v0, v1);
        sAL[o] = packh(v0 - h16f(v0), v1 - h16f(v1));
    }
    {   // vectorized B stage: tap0 -> B0
        const uint4* src = (const uint4*)g_w2pk;
#pragma unroll
        for (int i = tid; i < 1024; i += 256) {
            int kp = i >> 4, oc4 = (i & 15) * 4;
            *(uint4*)(sB0 + kp * 72 + oc4) = src[i];
        }
    }
    __syncthreads();

    // --- main: warp tile 32 rows (batch row bl) x 32 oc ---
    int bl = wid >> 1;
    int n0 = (wid & 1) * 32;

    float accH[2][4][4], accL[2][4][4];
#pragma unroll
    for (int mt = 0; mt < 2; mt++)
#pragma unroll
        for (int j = 0; j < 4; j++)
#pragma unroll
            for (int v = 0; v < 4; v++) { accH[mt][j][v] = 0.f; accL[mt][j][v] = 0.f; }

#define MMA_TAP(tap, SB) do { \
    _Pragma("unroll 2") \
    for (int kk = 0; kk < 8; kk++) { \
        int kb2 = kk * 8; \
        uint32_t AH[2][4], AL[2][4]; \
        _Pragma("unroll") \
        for (int mt = 0; mt < 2; mt++) { \
            int base = bl * 2312 + (mt * 16 + g + (tap)) * 68 + kb2 + q; \
            AH[mt][0] = sAH[base];       AL[mt][0] = sAL[base]; \
            AH[mt][1] = sAH[base + 544]; AL[mt][1] = sAL[base + 544]; \
            AH[mt][2] = sAH[base + 4];   AL[mt][2] = sAL[base + 4]; \
            AH[mt][3] = sAH[base + 548]; AL[mt][3] = sAL[base + 548]; \
        } \
        uint32_t B[4][2]; \
        _Pragma("unroll") \
        for (int j = 0; j < 4; j++) { \
            int n = n0 + 8 * j + g; \
            B[j][0] = (SB)[(kb2 + q) * 72 + n]; \
            B[j][1] = (SB)[(kb2 + q + 4) * 72 + n]; \
        } \
        _Pragma("unroll") \
        for (int mt = 0; mt < 2; mt++) \
            _Pragma("unroll") \
            for (int j = 0; j < 4; j++) \
                asm volatile( \
                    "mma.sync.aligned.m16n8k16.row.col.f32.f16.f16.f32 " \
                    "{%0,%1,%2,%3},{%4,%5,%6,%7},{%8,%9},{%0,%1,%2,%3};" \
                    : "+f"(accH[mt][j][0]), "+f"(accH[mt][j][1]), \
                      "+f"(accH[mt][j][2]), "+f"(accH[mt][j][3]) \
                    : "r"(AH[mt][0]), "r"(AH[mt][1]), "r"(AH[mt][2]), "r"(AH[mt][3]), \
                      "r"(B[j][0]), "r"(B[j][1])); \
        _Pragma("unroll") \
        for (int mt = 0; mt < 2; mt++) \
            _Pragma("unroll") \
            for (int j = 0; j < 4; j++) \
                asm volatile( \
                    "mma.sync.aligned.m16n8k16.row.col.f32.f16.f16.f32 " \
                    "{%0,%1,%2,%3},{%4,%5,%6,%7},{%8,%9},{%0,%1,%2,%3};" \
                    : "+f"(accL[mt][j][0]), "+f"(accL[mt][j][1]), \
                      "+f"(accL[mt][j][2]), "+f"(accL[mt][j][3]) \
                    : "r"(AL[mt][0]), "r"(AL[mt][1]), "r"(AL[mt][2]), "r"(AL[mt][3]), \
                      "r"(B[j][0]), "r"(B[j][1])); \
    } } while (0)

#define STAGE_B(tap, SB) do { \
    const uint4* src = (const uint4*)(g_w2pk + (tap) * 4096); \
    _Pragma("unroll") \
    for (int i = tid; i < 1024; i += 256) { \
        int kp = i >> 4, oc4 = (i & 15) * 4; \
        *(uint4*)((SB) + kp * 72 + oc4) = src[i]; \
    } } while (0)

    STAGE_B(1, sB1);
    MMA_TAP(0, sB0);
    __syncthreads();
    STAGE_B(2, sB0);
    MMA_TAP(1, sB1);
    __syncthreads();
    MMA_TAP(2, sB0);

    // --- epilogue: merge, bias+relu, store fp32 h2 [b][p][oc] via float2, stats ---
    __syncthreads();
    if (tid < 128) red[tid] = 0.f;
    __syncthreads();

    int b = bbase + bl;
    float bias[4][2];
#pragma unroll
    for (int j = 0; j < 4; j++) {
        bias[j][0] = __ldg(&b2[n0 + 8 * j + 2 * q]);
        bias[j][1] = __ldg(&b2[n0 + 8 * j + 2 * q + 1]);
    }
    float ssum[4][2], ssq[4][2];
#pragma unroll
    for (int j = 0; j < 4; j++)
        for (int c = 0; c < 2; c++) { ssum[j][c] = 0.f; ssq[j][c] = 0.f; }

    float2* h2v = (float2*)g_h2f;
#pragma unroll
    for (int mt = 0; mt < 2; mt++)
#pragma unroll
        for (int j = 0; j < 4; j++)
#pragma unroll
            for (int h = 0; h < 2; h++) {
                int p = mt * 16 + h * 8 + g;
                float y0 = fmaxf(accH[mt][j][h * 2 + 0] + accL[mt][j][h * 2 + 0] + bias[j][0], 0.f);
                float y1 = fmaxf(accH[mt][j][h * 2 + 1] + accL[mt][j][h * 2 + 1] + bias[j][1], 0.f);
                h2v[(b * 32 + p) * 32 + (n0 + 8 * j) / 2 + q] = make_float2(y0, y1);
                ssum[j][0] += y0; ssq[j][0] += y0 * y0;
                ssum[j][1] += y1; ssq[j][1] += y1 * y1;
            }
#pragma unroll
    for (int j = 0; j < 4; j++)
#pragma unroll
        for (int c = 0; c < 2; c++) {
#pragma unroll
            for (int mk = 4; mk <= 16; mk <<= 1) {
                ssum[j][c] += __shfl_xor_sync(0xffffffffu, ssum[j][c], mk);
                ssq[j][c]  += __shfl_xor_sync(0xffffffffu, ssq[j][c], mk);
            }
        }
    if (lid < 4) {
#pragma unroll
        for (int j = 0; j < 4; j++)
#pragma unroll
            for (int c = 0; c < 2; c++) {
                int oc = n0 + 8 * j + 2 * lid + c;
                atomicAdd(&red[oc], ssum[j][c]);
                atomicAdd(&red[64 + oc], ssq[j][c]);
            }
    }
    __syncthreads();
    if (tid < 128) atomicAdd(&g_stats2[tid], (double)red[tid]);
}

// ------------------------------------------------------------------
// conv3: sliding-scatter, NO smem staging. Thread = (b-local 0..15, oc-quad 0..15).
// Streams 32 rows of h2 [b][p][oc] (1 LDG.128 each, loaded exactly once),
// scatters into 32 register accumulators; butterfly-reduce over 16 quads;
// each lane emits 2 outputs with gated S constants.
__global__ void __launch_bounds__(256, 4)
k_conv3(const float* __restrict__ g2, const float* __restrict__ be2,
        const float* __restrict__ w3, const float* __restrict__ b3,
        float* __restrict__ out) {
    __shared__ float sw3a[192];
    __shared__ float sac[128];
    __shared__ float sS[3];

    int tid = threadIdx.x;
    if (tid < 64) {
        double N = 524288.0;
        double mean = g_stats2[tid] / N;
        double var = g_stats2[C2 + tid] / N - mean * mean;
        float a = g2[tid] * (float)(1.0 / sqrt(var + 1e-5));
        sac[tid] = a;
        sac[64 + tid] = be2[tid] - (float)mean * a;
    }
    __syncthreads();
    if (tid < 64) {
        float a = sac[tid];
        sw3a[tid * 3 + 0] = w3[tid * 3 + 0] * a;
        sw3a[tid * 3 + 1] = w3[tid * 3 + 1] * a;
        sw3a[tid * 3 + 2] = w3[tid * 3 + 2] * a;
    }
    if (tid < 3) {
        float s = 0.f;
        for (int ic = 0; ic < 64; ic++) s += w3[ic * 3 + tid] * sac[64 + ic];
        sS[tid] = s;
    }
    __syncthreads();

    int bl = tid >> 4;           // local batch row 0..15
    int quad = tid & 15;         // oc quad (4 channels)
    size_t bglob = (size_t)blockIdx.x * 16 + bl;
    const float4* src = (const float4*)(g_h2f + bglob * 32 * 64) + quad;

    float w[3][4];
#pragma unroll
    for (int c = 0; c < 4; c++) {
        int ic = quad * 4 + c;
        w[0][c] = sw3a[ic * 3 + 0];   // h2 row r -> out r-1
        w[1][c] = sw3a[ic * 3 + 1];   // -> out r
        w[2][c] = sw3a[ic * 3 + 2];   // -> out r+1
    }

    float acc[32];
#pragma unroll
    for (int p = 0; p < 32; p++) acc[p] = 0.f;

#pragma unroll
    for (int r = 0; r < 32; r++) {
        float4 v = src[r * 16];
        float dm = v.x * w[0][0] + v.y * w[0][1] + v.z * w[0][2] + v.w * w[0][3];
        float d0 = v.x * w[1][0] + v.y * w[1][1] + v.z * w[1][2] + v.w * w[1][3];
        float dp = v.x * w[2][0] + v.y * w[2][1] + v.z * w[2][2] + v.w * w[2][3];
        if (r > 0)  acc[r - 1] += dm;
        acc[r] += d0;
        if (r < 31) acc[r + 1] += dp;
    }

#pragma unroll
    for (int mk = 1; mk <= 8; mk <<= 1)
#pragma unroll
        for (int p = 0; p < 32; p++)
            acc[p] += __shfl_xor_sync(0xffffffffu, acc[p], mk);

    float base = __ldg(&b3[0]) + sS[1];
#pragma unroll
    for (int e = 0; e < 2; e++) {
        int p = quad * 2 + e;
        float a = acc[p] + base + (p > 0 ? sS[2] : 0.f) + (p < 31 ? sS[0] : 0.f);
        out[bglob * 32 + p] = tanhf(a);
    }
}

// ------------------------------------------------------------------
extern "C" void kernel_launch(void* const* d_in, const int* in_sizes, int n_in,
                              void* d_out, int out_size) {
    const float* x   = (const float*)d_in[0];
    const float* qp  = (const float*)d_in[1];
    const float* w1  = (const float*)d_in[2];
    const float* b1  = (const float*)d_in[3];
    const float* g1  = (const float*)d_in[4];
    const float* be1 = (const float*)d_in[5];
    const float* w2  = (const float*)d_in[6];
    const float* b2  = (const float*)d_in[7];
    const float* g2  = (const float*)d_in[8];
    const float* be2 = (const float*)d_in[9];
    const float* w3  = (const float*)d_in[10];
    const float* b3  = (const float*)d_in[11];
    float* out = (float*)d_out;

    const int smem_bytes = SM_FLOATS * (int)sizeof(float);   // 110848 B
    cudaFuncSetAttribute(k_conv2, cudaFuncAttributeMaxDynamicSharedMemorySize, smem_bytes);

    k_prep<<<1, 256>>>(w2);
    k_imgstats<<<BSZ / 32, 256>>>(x, qp, w1, b1);
    k_conv2<<<BSZ / 4, 256, smem_bytes>>>(w1, b1, g1, be1, b2);
    k_conv3<<<BSZ / 16, 256>>>(g2, be2, w3, b3, out);
}